// round 1
// baseline (speedup 1.0000x reference)
#include <cuda_runtime.h>
#include <math.h>

// ---------------- problem constants ----------------
#define DIMN 1024
#define HIDN 2048
#define BB   4
#define SS   2048
#define CHK  64
#define NCH  32        // SS/CHK
#define BC   256       // BB*CHK
#define NTOK 8192      // BB*SS
#define EPSN 1e-8f
#define SCALE_CONST (2.0f/(BB*CHK*DIMN))

// ---------------- device scratch (no runtime allocs allowed) ----------------
__device__ float g_kp[NCH*BC*DIMN];   // k, permuted [nch][B*C][D]
__device__ float g_vp[NCH*BC*DIMN];   // v, permuted
__device__ float g_qp[NCH*BC*DIMN];   // q, permuted
__device__ float g_h1[BC*HIDN];
__device__ float g_a1[BC*HIDN];
__device__ float g_d2[BC*DIMN];
__device__ float g_d1[BC*HIDN];
__device__ float g_aq[BC*HIDN];
__device__ float g_y [NTOK*DIMN];     // natural [B,S,D]
__device__ float g_w1a[HIDN*DIMN];
__device__ float g_w1b[HIDN*DIMN];
__device__ float g_w2a[DIMN*HIDN];
__device__ float g_w2b[DIMN*HIDN];
__device__ float g_m1 [HIDN*DIMN];
__device__ float g_m2 [DIMN*HIDN];
__device__ float g_gate_tok[NTOK*3];
__device__ float g_gates[NCH*3];      // per-chunk: lr, alpha, eta

// ---------------- math helpers ----------------
__device__ __forceinline__ float sigf(float x){ return 1.0f/(1.0f+expf(-x)); }
__device__ __forceinline__ float siluf(float x){ return x*sigf(x); }
__device__ __forceinline__ float siluderivf(float x){ float s=sigf(x); return s*(1.0f + x*(1.0f-s)); }
__device__ __forceinline__ float clip1f(float x){ return fminf(fmaxf(x,-1.0f),1.0f); }

// ---------------- generic tiled fp32 GEMM: C[M,N] = sum_k A(m,k)*B(n,k) ----------------
// AKM: A stored [M,K] row-major (K contiguous), else [K,M] with lda = M-row stride.
// BKM: B stored [N,K] row-major (K contiguous), else [K,N] with ldb = N-row stride.
// Epilogues:
//  0: C = acc
//  1: C = acc, aux1 = silu(acc)                       (h1 / a1)
//  2: C = scale * clip(acc - aux0, +-1)               (d2 from pred & v)
//  3: C = acc * silu'(aux0)                           (d1, aux0 = h1)
//  4: g = clip(acc); mn = eta*aux1 - lr*g; aux1 = mn; C = (1-alpha)*aux0 + mn  (weight update)
//  5: C = silu(acc)                                   (retrieval hidden)
//  6: C = acc written at row (m>>6)*SS + base + (m&63)       (y chunk -> natural layout)
//  7: C = silu(acc) written at permuted row (chunk layout)   (projections)
template<int BM,int BN,bool AKM,bool BKM,int EP>
__global__ __launch_bounds__((BM/4)*(BN/4))
void gemm_k(const float* __restrict__ A, int lda,
            const float* __restrict__ Bp, int ldb,
            float* __restrict__ C, int ldc, int K,
            const float* __restrict__ aux0,
            float* __restrict__ aux1,
            const float* __restrict__ gates,
            float scale, int base)
{
    constexpr int BKT = 16;
    constexpr int NT  = (BM/4)*(BN/4);
    __shared__ __align__(16) float As[BKT][BM+4];
    __shared__ __align__(16) float Bs[BKT][BN+4];

    const int tid = threadIdx.x;
    const int tx  = tid % (BN/4);
    const int ty  = tid / (BN/4);
    const int m0  = blockIdx.y * BM;
    const int n0  = blockIdx.x * BN;

    float acc[4][4] = {};

    for (int k0 = 0; k0 < K; k0 += BKT) {
        // ---- load A tile into As[k][m] ----
        if constexpr (AKM) {
            #pragma unroll
            for (int i = tid; i < BM*(BKT/4); i += NT) {
                int m  = i / (BKT/4);
                int kq = i % (BKT/4);
                float4 v = *(const float4*)(A + (size_t)(m0+m)*lda + k0 + kq*4);
                As[kq*4+0][m] = v.x; As[kq*4+1][m] = v.y;
                As[kq*4+2][m] = v.z; As[kq*4+3][m] = v.w;
            }
        } else {
            #pragma unroll
            for (int i = tid; i < (BM/4)*BKT; i += NT) {
                int k  = i / (BM/4);
                int mq = i % (BM/4);
                *(float4*)&As[k][mq*4] = *(const float4*)(A + (size_t)(k0+k)*lda + m0 + mq*4);
            }
        }
        // ---- load B tile into Bs[k][n] ----
        if constexpr (BKM) {
            #pragma unroll
            for (int i = tid; i < BN*(BKT/4); i += NT) {
                int n  = i / (BKT/4);
                int kq = i % (BKT/4);
                float4 v = *(const float4*)(Bp + (size_t)(n0+n)*ldb + k0 + kq*4);
                Bs[kq*4+0][n] = v.x; Bs[kq*4+1][n] = v.y;
                Bs[kq*4+2][n] = v.z; Bs[kq*4+3][n] = v.w;
            }
        } else {
            #pragma unroll
            for (int i = tid; i < (BN/4)*BKT; i += NT) {
                int k  = i / (BN/4);
                int nq = i % (BN/4);
                *(float4*)&Bs[k][nq*4] = *(const float4*)(Bp + (size_t)(k0+k)*ldb + n0 + nq*4);
            }
        }
        __syncthreads();

        #pragma unroll
        for (int k = 0; k < BKT; ++k) {
            float4 a = *(const float4*)&As[k][ty*4];
            float4 b = *(const float4*)&Bs[k][tx*4];
            acc[0][0]+=a.x*b.x; acc[0][1]+=a.x*b.y; acc[0][2]+=a.x*b.z; acc[0][3]+=a.x*b.w;
            acc[1][0]+=a.y*b.x; acc[1][1]+=a.y*b.y; acc[1][2]+=a.y*b.z; acc[1][3]+=a.y*b.w;
            acc[2][0]+=a.z*b.x; acc[2][1]+=a.z*b.y; acc[2][2]+=a.z*b.z; acc[2][3]+=a.z*b.w;
            acc[3][0]+=a.w*b.x; acc[3][1]+=a.w*b.y; acc[3][2]+=a.w*b.z; acc[3][3]+=a.w*b.w;
        }
        __syncthreads();
    }

    // ---- epilogue ----
    float lr = 0.f, al = 0.f, et = 0.f;
    if (EP == 4) { lr = gates[0]; al = gates[1]; et = gates[2]; }

    #pragma unroll
    for (int i = 0; i < 4; ++i) {
        int m = m0 + ty*4 + i;
        size_t crow;
        if (EP == 6) {                        // y chunk -> natural [B,S,D]
            int b = m >> 6, ci = m & 63;
            crow = (size_t)(b*SS + base + ci) * ldc;
        } else if (EP == 7) {                 // token -> chunk-permuted layout
            int b = m >> 11, s = m & (SS-1);
            crow = (size_t)((s >> 6)*BC + b*CHK + (s & 63)) * ldc;
        } else {
            crow = (size_t)m * ldc;
        }
        size_t srow = (size_t)m * ldc;        // aux arrays share the un-remapped layout
        #pragma unroll
        for (int j = 0; j < 4; ++j) {
            int n = n0 + tx*4 + j;
            float v = acc[i][j];
            size_t idx  = crow + n;
            size_t sidx = srow + n;
            if      (EP == 0) C[idx] = v;
            else if (EP == 1) { C[idx] = v; aux1[idx] = siluf(v); }
            else if (EP == 2) { C[idx] = scale * clip1f(v - aux0[sidx]); }
            else if (EP == 3) { C[idx] = v * siluderivf(aux0[sidx]); }
            else if (EP == 4) {
                float g  = clip1f(v);
                float mn = et * aux1[idx] - lr * g;
                aux1[idx] = mn;
                C[idx] = (1.0f - al) * aux0[idx] + mn;
            }
            else if (EP == 5) C[idx] = siluf(v);
            else if (EP == 6) C[idx] = v;
            else if (EP == 7) C[idx] = siluf(v);
        }
    }
}

// ---------------- row-wise l2 normalize (in place), D = 1024, block = 256 ----------------
__global__ void l2norm_k(float* __restrict__ p)
{
    int row = blockIdx.x;
    float* r = p + (size_t)row * DIMN;
    int t = threadIdx.x;
    float4 v = *(float4*)(r + t*4);
    float ss = v.x*v.x + v.y*v.y + v.z*v.z + v.w*v.w;
    __shared__ float red[256];
    red[t] = ss; __syncthreads();
    for (int o = 128; o > 0; o >>= 1) { if (t < o) red[t] += red[t+o]; __syncthreads(); }
    float inv = rsqrtf(red[0] + EPSN);
    v.x *= inv; v.y *= inv; v.z *= inv; v.w *= inv;
    *(float4*)(r + t*4) = v;
}

// ---------------- per-token gate dots: sigmoid(x . w + b), 3 gates ----------------
__global__ void gate_tok_k(const float* __restrict__ x,
                           const float* __restrict__ wlr,  const float* __restrict__ blr,
                           const float* __restrict__ wdec, const float* __restrict__ bdec,
                           const float* __restrict__ wmom, const float* __restrict__ bmom)
{
    int tok = blockIdx.x;
    int t = threadIdx.x;   // 256
    const float* xr = x + (size_t)tok * DIMN;
    float s0 = 0.f, s1 = 0.f, s2 = 0.f;
    for (int i = t; i < DIMN; i += 256) {
        float xi = xr[i];
        s0 += xi * wlr[i]; s1 += xi * wdec[i]; s2 += xi * wmom[i];
    }
    __shared__ float r0[256], r1[256], r2[256];
    r0[t] = s0; r1[t] = s1; r2[t] = s2; __syncthreads();
    for (int o = 128; o > 0; o >>= 1) {
        if (t < o) { r0[t] += r0[t+o]; r1[t] += r1[t+o]; r2[t] += r2[t+o]; }
        __syncthreads();
    }
    if (t == 0) {
        g_gate_tok[tok*3+0] = sigf(r0[0] + blr[0]);
        g_gate_tok[tok*3+1] = sigf(r1[0] + bdec[0]);
        g_gate_tok[tok*3+2] = sigf(r2[0] + bmom[0]);
    }
}

// ---------------- per-chunk gate means over (batch, chunk-pos): 256 tokens ----------------
__global__ void gate_chunk_k()
{
    int ch = blockIdx.x;
    int t = threadIdx.x;   // 256
    int b = t >> 6, ci = t & 63;
    int tok = b*SS + ch*CHK + ci;
    __shared__ float r0[256], r1[256], r2[256];
    r0[t] = g_gate_tok[tok*3+0];
    r1[t] = g_gate_tok[tok*3+1];
    r2[t] = g_gate_tok[tok*3+2];
    __syncthreads();
    for (int o = 128; o > 0; o >>= 1) {
        if (t < o) { r0[t] += r0[t+o]; r1[t] += r1[t+o]; r2[t] += r2[t+o]; }
        __syncthreads();
    }
    if (t == 0) {
        g_gates[ch*3+0] = r0[0] * (1.0f/BC);
        g_gates[ch*3+1] = r1[0] * (1.0f/BC);
        g_gates[ch*3+2] = r2[0] * (1.0f/BC);
    }
}

// ---------------- host orchestration ----------------
extern "C" void kernel_launch(void* const* d_in, const int* in_sizes, int n_in,
                              void* d_out, int out_size)
{
    const float* x    = (const float*)d_in[0];
    const float* Wk   = (const float*)d_in[1];
    const float* Wv   = (const float*)d_in[2];
    const float* Wq   = (const float*)d_in[3];
    const float* Wout = (const float*)d_in[4];
    const float* W1   = (const float*)d_in[5];
    const float* W2   = (const float*)d_in[6];
    const float* Wlr  = (const float*)d_in[7];
    const float* blr  = (const float*)d_in[8];
    const float* Wdec = (const float*)d_in[9];
    const float* bdec = (const float*)d_in[10];
    const float* Wmom = (const float*)d_in[11];
    const float* bmom = (const float*)d_in[12];
    float* out = (float*)d_out;

    float *kp,*vp,*qp,*h1,*a1,*d2,*d1,*aq,*y,*w1A,*w1B,*w2A,*w2B,*m1,*m2,*gch;
    cudaGetSymbolAddress((void**)&kp,  g_kp);
    cudaGetSymbolAddress((void**)&vp,  g_vp);
    cudaGetSymbolAddress((void**)&qp,  g_qp);
    cudaGetSymbolAddress((void**)&h1,  g_h1);
    cudaGetSymbolAddress((void**)&a1,  g_a1);
    cudaGetSymbolAddress((void**)&d2,  g_d2);
    cudaGetSymbolAddress((void**)&d1,  g_d1);
    cudaGetSymbolAddress((void**)&aq,  g_aq);
    cudaGetSymbolAddress((void**)&y,   g_y);
    cudaGetSymbolAddress((void**)&w1A, g_w1a);
    cudaGetSymbolAddress((void**)&w1B, g_w1b);
    cudaGetSymbolAddress((void**)&w2A, g_w2a);
    cudaGetSymbolAddress((void**)&w2B, g_w2b);
    cudaGetSymbolAddress((void**)&m1,  g_m1);
    cudaGetSymbolAddress((void**)&m2,  g_m2);
    cudaGetSymbolAddress((void**)&gch, g_gates);

    // zero momentum each call (deterministic)
    cudaMemsetAsync(m1, 0, sizeof(float)*HIDN*DIMN);
    cudaMemsetAsync(m2, 0, sizeof(float)*DIMN*HIDN);

    // gates
    gate_tok_k<<<NTOK, 256>>>(x, Wlr, blr, Wdec, bdec, Wmom, bmom);
    gate_chunk_k<<<NCH, 256>>>();

    // projections (silu + chunk-permuted store), then l2norm for k and q
    dim3 gproj(DIMN/64, NTOK/64);
    gemm_k<64,64,true,true,7><<<gproj,256>>>(x, DIMN, Wk, DIMN, kp, DIMN, DIMN, nullptr, nullptr, nullptr, 0.f, 0);
    gemm_k<64,64,true,true,7><<<gproj,256>>>(x, DIMN, Wv, DIMN, vp, DIMN, DIMN, nullptr, nullptr, nullptr, 0.f, 0);
    gemm_k<64,64,true,true,7><<<gproj,256>>>(x, DIMN, Wq, DIMN, qp, DIMN, DIMN, nullptr, nullptr, nullptr, 0.f, 0);
    l2norm_k<<<NTOK,256>>>(kp);
    l2norm_k<<<NTOK,256>>>(qp);

    for (int ch = 0; ch < NCH; ++ch) {
        const float* kt = kp + (size_t)ch*BC*DIMN;
        const float* vt = vp + (size_t)ch*BC*DIMN;
        const float* qt = qp + (size_t)ch*BC*DIMN;
        const float* w1c = (ch == 0) ? W1 : ((ch & 1) ? w1A : w1B);
        const float* w2c = (ch == 0) ? W2 : ((ch & 1) ? w2A : w2B);
        float* w1n = (ch & 1) ? w1B : w1A;
        float* w2n = (ch & 1) ? w2B : w2A;
        const float* gp3 = gch + ch*3;

        // 1) h1 = kt @ w1^T ; a1 = silu(h1)
        gemm_k<32,64,true,true,1><<<dim3(HIDN/64, BC/32),128>>>(
            kt, DIMN, w1c, DIMN, h1, HIDN, DIMN, nullptr, a1, nullptr, 0.f, 0);
        // 2) d2 = scale * clip(a1 @ w2^T - v)
        gemm_k<32,64,true,true,2><<<dim3(DIMN/64, BC/32),128>>>(
            a1, HIDN, w2c, HIDN, d2, DIMN, HIDN, vt, nullptr, nullptr, SCALE_CONST, 0);
        // 3) d1 = (d2 @ w2) * silu'(h1)     (B is [K=D, N=H] -> BKM=false)
        gemm_k<32,64,true,false,3><<<dim3(HIDN/64, BC/32),128>>>(
            d2, DIMN, w2c, HIDN, d1, HIDN, DIMN, h1, nullptr, nullptr, 0.f, 0);
        // 4) w2 update: g2[d,h] = sum_bc d2^T a1 ; momentum/decay fused
        gemm_k<64,64,false,false,4><<<dim3(HIDN/64, DIMN/64),256>>>(
            d2, DIMN, a1, HIDN, w2n, HIDN, BC, w2c, m2, gp3, 0.f, 0);
        // 5) w1 update: g1[h,d] = sum_bc d1^T kt
        gemm_k<64,64,false,false,4><<<dim3(DIMN/64, HIDN/64),256>>>(
            d1, HIDN, kt, DIMN, w1n, DIMN, BC, w1c, m1, gp3, 0.f, 0);
        // 6) aq = silu(qt @ w1n^T)
        gemm_k<32,64,true,true,5><<<dim3(HIDN/64, BC/32),128>>>(
            qt, DIMN, w1n, DIMN, aq, HIDN, DIMN, nullptr, nullptr, nullptr, 0.f, 0);
        // 7) y_chunk = aq @ w2n^T  -> natural [B,S,D] layout
        gemm_k<32,64,true,true,6><<<dim3(DIMN/64, BC/32),128>>>(
            aq, HIDN, w2n, HIDN, y, DIMN, HIDN, nullptr, nullptr, nullptr, 0.f, ch*CHK);
    }

    // out = y @ Wout^T
    gemm_k<64,64,true,true,0><<<dim3(DIMN/64, NTOK/64),256>>>(
        y, DIMN, Wout, DIMN, out, DIMN, DIMN, nullptr, nullptr, nullptr, 0.f, 0);
}

// round 3
// speedup vs baseline: 1.1794x; 1.1794x over previous
#include <cuda_runtime.h>
#include <cuda_bf16.h>
#include <math.h>

// ---------------- problem constants ----------------
#define DIMN 1024
#define HIDN 2048
#define BB   4
#define SS   2048
#define CHK  64
#define NCH  32        // SS/CHK
#define BC   256       // BB*CHK
#define NTOK 8192      // BB*SS
#define EPSN 1e-8f
#define SCALE_CONST (2.0f/(BB*CHK*DIMN))

// ---------------- device scratch (no runtime allocs allowed) ----------------
__device__ float g_kp[NCH*BC*DIMN];   // k, permuted [nch][B*C][D]
__device__ float g_vp[NCH*BC*DIMN];   // v, permuted
__device__ float g_qp[NCH*BC*DIMN];   // q, permuted
__device__ float g_h1[BC*HIDN];
__device__ float g_a1[BC*HIDN];
__device__ float g_d2[BC*DIMN];
__device__ float g_d1[BC*HIDN];
__device__ float g_aq[BC*HIDN];
__device__ float g_y [NTOK*DIMN];     // natural [B,S,D]
__device__ float g_w1a[HIDN*DIMN];
__device__ float g_w1b[HIDN*DIMN];
__device__ float g_w2a[DIMN*HIDN];
__device__ float g_w2b[DIMN*HIDN];
__device__ float g_m1 [HIDN*DIMN];
__device__ float g_m2 [DIMN*HIDN];
__device__ float g_gate_tok[NTOK*3];
__device__ float g_gates[NCH*3];      // per-chunk: lr, alpha, eta

// ---------------- math helpers ----------------
__device__ __forceinline__ float sigf(float x){ return 1.0f/(1.0f+expf(-x)); }
__device__ __forceinline__ float siluf(float x){ return x*sigf(x); }
__device__ __forceinline__ float siluderivf(float x){ float s=sigf(x); return s*(1.0f + x*(1.0f-s)); }
__device__ __forceinline__ float clip1f(float x){ return fminf(fmaxf(x,-1.0f),1.0f); }

// ---------------- bf16 mma.sync core ----------------
__device__ __forceinline__ void mma_bf16(float* d, const unsigned* a, const unsigned* b){
    asm volatile(
        "mma.sync.aligned.m16n8k16.row.col.f32.bf16.bf16.f32 "
        "{%0,%1,%2,%3}, {%4,%5,%6,%7}, {%8,%9}, {%0,%1,%2,%3};\n"
        : "+f"(d[0]), "+f"(d[1]), "+f"(d[2]), "+f"(d[3])
        : "r"(a[0]), "r"(a[1]), "r"(a[2]), "r"(a[3]), "r"(b[0]), "r"(b[1]));
}

// Load a [R x KC] fp32 tile into hi/lo bf16 smem tiles, layout S[r*KS + k] (k contiguous).
// KM=true: source is [rows][K] k-contiguous. KM=false: source is [K][rows] r-contiguous (transpose load).
template<int R, bool KM, int KC, int KS>
__device__ __forceinline__ void load_tile(const float* __restrict__ P, int ld,
                                          int r0, int k0,
                                          __nv_bfloat16* __restrict__ Sh,
                                          __nv_bfloat16* __restrict__ Sl,
                                          int tid)
{
    if constexpr (KM) {
        #pragma unroll
        for (int i = tid; i < R*(KC/4); i += 128) {
            int r  = i / (KC/4);
            int kq = (i % (KC/4)) * 4;
            float4 v = *(const float4*)(P + (size_t)(r0+r)*ld + k0 + kq);
            float f[4] = {v.x, v.y, v.z, v.w};
            #pragma unroll
            for (int j = 0; j < 2; ++j) {
                __nv_bfloat16 h0 = __float2bfloat16_rn(f[j*2+0]);
                __nv_bfloat16 h1 = __float2bfloat16_rn(f[j*2+1]);
                __nv_bfloat162 hp; hp.x = h0; hp.y = h1;
                __nv_bfloat162 lp;
                lp.x = __float2bfloat16_rn(f[j*2+0] - __bfloat162float(h0));
                lp.y = __float2bfloat16_rn(f[j*2+1] - __bfloat162float(h1));
                *(__nv_bfloat162*)(Sh + r*KS + kq + j*2) = hp;
                *(__nv_bfloat162*)(Sl + r*KS + kq + j*2) = lp;
            }
        }
    } else {
        #pragma unroll
        for (int i = tid; i < (R/4)*KC; i += 128) {
            int k  = i / (R/4);
            int rq = (i % (R/4)) * 4;
            float4 v = *(const float4*)(P + (size_t)(k0+k)*ld + r0 + rq);
            float f[4] = {v.x, v.y, v.z, v.w};
            #pragma unroll
            for (int j = 0; j < 4; ++j) {
                __nv_bfloat16 h = __float2bfloat16_rn(f[j]);
                Sh[(rq+j)*KS + k] = h;
                Sl[(rq+j)*KS + k] = __float2bfloat16_rn(f[j] - __bfloat162float(h));
            }
        }
    }
}

// ---------------- tensor-core GEMM: C[M,N] = sum_k A(m,k)*B(n,k) ----------------
// AKM/BKM: operand stored k-contiguous ([rows][K]) if true, else [K][rows].
// Epilogues:
//  0: C = acc
//  1: C = acc, aux1 = silu(acc)
//  2: C = scale * clip(acc - aux0, +-1)
//  3: C = acc * silu'(aux0)
//  4: g = clip(acc); mn = eta*aux1 - lr*g; aux1 = mn; C = (1-alpha)*aux0 + mn
//  5: C = silu(acc)
//  6: C = acc written at natural-layout row (chunk -> [B,S,D])
//  7: C = silu(acc) written at chunk-permuted row (token -> chunk layout)
template<int BM,int BN,bool AKM,bool BKM,int EP>
__global__ __launch_bounds__(128)
void mgemm_k(const float* __restrict__ A, int lda,
             const float* __restrict__ Bp, int ldb,
             float* __restrict__ C, int ldc, int K,
             const float* __restrict__ aux0,
             float* __restrict__ aux1,
             const float* __restrict__ gates,
             float scale, int base)
{
    constexpr int KC = 32;
    constexpr int KS = KC + 4;
    constexpr int NI = (BM == 64) ? 4 : 2;    // mma n-tiles per warp

    __shared__ __nv_bfloat16 sAh[BM*KS], sAl[BM*KS];
    __shared__ __nv_bfloat16 sBh[BN*KS], sBl[BN*KS];

    const int tid  = threadIdx.x;
    const int lane = tid & 31;
    const int wid  = tid >> 5;
    const int g    = lane >> 2;
    const int tg   = lane & 3;
    // warp tiling: BM=64 -> 2x2 warps of 32x32; BM=32 -> 1x4 warps of 32x16
    const int wm = (BM == 64) ? (wid >> 1) * 32 : 0;
    const int wn = (BM == 64) ? (wid & 1) * 32 : wid * 16;
    const int m0 = blockIdx.y * BM;
    const int n0 = blockIdx.x * BN;

    float acc[2][NI][4] = {};

    for (int k0 = 0; k0 < K; k0 += KC) {
        load_tile<BM,AKM,KC,KS>(A,  lda, m0, k0, sAh, sAl, tid);
        load_tile<BN,BKM,KC,KS>(Bp, ldb, n0, k0, sBh, sBl, tid);
        __syncthreads();

        #pragma unroll
        for (int kt = 0; kt < KC; kt += 16) {
            unsigned ah[2][4], al[2][4], bh[NI][2], bl[NI][2];
            #pragma unroll
            for (int mi = 0; mi < 2; ++mi) {
                int o = (wm + mi*16 + g)*KS + kt + tg*2;
                ah[mi][0] = *(const unsigned*)(sAh + o);
                ah[mi][1] = *(const unsigned*)(sAh + o + 8*KS);
                ah[mi][2] = *(const unsigned*)(sAh + o + 8);
                ah[mi][3] = *(const unsigned*)(sAh + o + 8*KS + 8);
                al[mi][0] = *(const unsigned*)(sAl + o);
                al[mi][1] = *(const unsigned*)(sAl + o + 8*KS);
                al[mi][2] = *(const unsigned*)(sAl + o + 8);
                al[mi][3] = *(const unsigned*)(sAl + o + 8*KS + 8);
            }
            #pragma unroll
            for (int ni = 0; ni < NI; ++ni) {
                int o = (wn + ni*8 + g)*KS + kt + tg*2;
                bh[ni][0] = *(const unsigned*)(sBh + o);
                bh[ni][1] = *(const unsigned*)(sBh + o + 8);
                bl[ni][0] = *(const unsigned*)(sBl + o);
                bl[ni][1] = *(const unsigned*)(sBl + o + 8);
            }
            #pragma unroll
            for (int mi = 0; mi < 2; ++mi)
                #pragma unroll
                for (int ni = 0; ni < NI; ++ni) {
                    mma_bf16(acc[mi][ni], ah[mi], bh[ni]);   // hi*hi
                    mma_bf16(acc[mi][ni], ah[mi], bl[ni]);   // hi*lo
                    mma_bf16(acc[mi][ni], al[mi], bh[ni]);   // lo*hi
                }
        }
        __syncthreads();
    }

    // ---- epilogue ----
    float lrg = 0.f, alg = 0.f, etg = 0.f;
    if (EP == 4) { lrg = gates[0]; alg = gates[1]; etg = gates[2]; }

    #pragma unroll
    for (int mi = 0; mi < 2; ++mi)
    #pragma unroll
    for (int rr = 0; rr < 2; ++rr) {
        int m = m0 + wm + mi*16 + rr*8 + g;
        size_t crow;
        if (EP == 6) {                        // chunk -> natural [B,S,D]
            int b = m >> 6, ci = m & 63;
            crow = (size_t)(b*SS + base + ci) * ldc;
        } else if (EP == 7) {                 // token -> chunk-permuted
            int b = m >> 11, s = m & (SS-1);
            crow = (size_t)((s >> 6)*BC + b*CHK + (s & 63)) * ldc;
        } else {
            crow = (size_t)m * ldc;
        }
        size_t srow = (size_t)m * ldc;
        #pragma unroll
        for (int ni = 0; ni < NI; ++ni) {
            int n = n0 + wn + ni*8 + tg*2;
            #pragma unroll
            for (int cc = 0; cc < 2; ++cc) {
                float v = acc[mi][ni][rr*2 + cc];
                size_t idx  = crow + n + cc;
                size_t sidx = srow + n + cc;
                if      (EP == 0) C[idx] = v;
                else if (EP == 1) { C[idx] = v; aux1[idx] = siluf(v); }
                else if (EP == 2) { C[idx] = scale * clip1f(v - aux0[sidx]); }
                else if (EP == 3) { C[idx] = v * siluderivf(aux0[sidx]); }
                else if (EP == 4) {
                    float gg = clip1f(v);
                    float mn = etg * aux1[idx] - lrg * gg;
                    aux1[idx] = mn;
                    C[idx] = (1.0f - alg) * aux0[idx] + mn;
                }
                else if (EP == 5) C[idx] = siluf(v);
                else if (EP == 6) C[idx] = v;
                else if (EP == 7) C[idx] = siluf(v);
            }
        }
    }
}

// ---------------- row-wise l2 normalize (in place), D = 1024, block = 256 ----------------
__global__ void l2norm_k(float* __restrict__ p)
{
    int row = blockIdx.x;
    float* r = p + (size_t)row * DIMN;
    int t = threadIdx.x;
    float4 v = *(float4*)(r + t*4);
    float ss = v.x*v.x + v.y*v.y + v.z*v.z + v.w*v.w;
    __shared__ float red[256];
    red[t] = ss; __syncthreads();
    for (int o = 128; o > 0; o >>= 1) { if (t < o) red[t] += red[t+o]; __syncthreads(); }
    float inv = rsqrtf(red[0] + EPSN);
    v.x *= inv; v.y *= inv; v.z *= inv; v.w *= inv;
    *(float4*)(r + t*4) = v;
}

// ---------------- per-token gate dots: sigmoid(x . w + b), 3 gates ----------------
__global__ void gate_tok_k(const float* __restrict__ x,
                           const float* __restrict__ wlr,  const float* __restrict__ blr,
                           const float* __restrict__ wdec, const float* __restrict__ bdec,
                           const float* __restrict__ wmom, const float* __restrict__ bmom)
{
    int tok = blockIdx.x;
    int t = threadIdx.x;   // 256
    const float* xr = x + (size_t)tok * DIMN;
    float s0 = 0.f, s1 = 0.f, s2 = 0.f;
    for (int i = t; i < DIMN; i += 256) {
        float xi = xr[i];
        s0 += xi * wlr[i]; s1 += xi * wdec[i]; s2 += xi * wmom[i];
    }
    __shared__ float r0[256], r1[256], r2[256];
    r0[t] = s0; r1[t] = s1; r2[t] = s2; __syncthreads();
    for (int o = 128; o > 0; o >>= 1) {
        if (t < o) { r0[t] += r0[t+o]; r1[t] += r1[t+o]; r2[t] += r2[t+o]; }
        __syncthreads();
    }
    if (t == 0) {
        g_gate_tok[tok*3+0] = sigf(r0[0] + blr[0]);
        g_gate_tok[tok*3+1] = sigf(r1[0] + bdec[0]);
        g_gate_tok[tok*3+2] = sigf(r2[0] + bmom[0]);
    }
}

// ---------------- per-chunk gate means over (batch, chunk-pos): 256 tokens ----------------
__global__ void gate_chunk_k()
{
    int ch = blockIdx.x;
    int t = threadIdx.x;   // 256
    int b = t >> 6, ci = t & 63;
    int tok = b*SS + ch*CHK + ci;
    __shared__ float r0[256], r1[256], r2[256];
    r0[t] = g_gate_tok[tok*3+0];
    r1[t] = g_gate_tok[tok*3+1];
    r2[t] = g_gate_tok[tok*3+2];
    __syncthreads();
    for (int o = 128; o > 0; o >>= 1) {
        if (t < o) { r0[t] += r0[t+o]; r1[t] += r1[t+o]; r2[t] += r2[t+o]; }
        __syncthreads();
    }
    if (t == 0) {
        g_gates[ch*3+0] = r0[0] * (1.0f/BC);
        g_gates[ch*3+1] = r1[0] * (1.0f/BC);
        g_gates[ch*3+2] = r2[0] * (1.0f/BC);
    }
}

// ---------------- host orchestration ----------------
extern "C" void kernel_launch(void* const* d_in, const int* in_sizes, int n_in,
                              void* d_out, int out_size)
{
    const float* x    = (const float*)d_in[0];
    const float* Wk   = (const float*)d_in[1];
    const float* Wv   = (const float*)d_in[2];
    const float* Wq   = (const float*)d_in[3];
    const float* Wout = (const float*)d_in[4];
    const float* W1   = (const float*)d_in[5];
    const float* W2   = (const float*)d_in[6];
    const float* Wlr  = (const float*)d_in[7];
    const float* blr  = (const float*)d_in[8];
    const float* Wdec = (const float*)d_in[9];
    const float* bdec = (const float*)d_in[10];
    const float* Wmom = (const float*)d_in[11];
    const float* bmom = (const float*)d_in[12];
    float* out = (float*)d_out;

    float *kp,*vp,*qp,*h1,*a1,*d2,*d1,*aq,*y,*w1A,*w1B,*w2A,*w2B,*m1,*m2,*gch;
    cudaGetSymbolAddress((void**)&kp,  g_kp);
    cudaGetSymbolAddress((void**)&vp,  g_vp);
    cudaGetSymbolAddress((void**)&qp,  g_qp);
    cudaGetSymbolAddress((void**)&h1,  g_h1);
    cudaGetSymbolAddress((void**)&a1,  g_a1);
    cudaGetSymbolAddress((void**)&d2,  g_d2);
    cudaGetSymbolAddress((void**)&d1,  g_d1);
    cudaGetSymbolAddress((void**)&aq,  g_aq);
    cudaGetSymbolAddress((void**)&y,   g_y);
    cudaGetSymbolAddress((void**)&w1A, g_w1a);
    cudaGetSymbolAddress((void**)&w1B, g_w1b);
    cudaGetSymbolAddress((void**)&w2A, g_w2a);
    cudaGetSymbolAddress((void**)&w2B, g_w2b);
    cudaGetSymbolAddress((void**)&m1,  g_m1);
    cudaGetSymbolAddress((void**)&m2,  g_m2);
    cudaGetSymbolAddress((void**)&gch, g_gates);

    // zero momentum each call (deterministic)
    cudaMemsetAsync(m1, 0, sizeof(float)*HIDN*DIMN);
    cudaMemsetAsync(m2, 0, sizeof(float)*DIMN*HIDN);

    // gates
    gate_tok_k<<<NTOK, 256>>>(x, Wlr, blr, Wdec, bdec, Wmom, bmom);
    gate_chunk_k<<<NCH, 256>>>();

    // projections (silu + chunk-permuted store), then l2norm for k and q
    dim3 gproj(DIMN/64, NTOK/64);
    mgemm_k<64,64,true,true,7><<<gproj,128>>>(x, DIMN, Wk, DIMN, kp, DIMN, DIMN, nullptr, nullptr, nullptr, 0.f, 0);
    mgemm_k<64,64,true,true,7><<<gproj,128>>>(x, DIMN, Wv, DIMN, vp, DIMN, DIMN, nullptr, nullptr, nullptr, 0.f, 0);
    mgemm_k<64,64,true,true,7><<<gproj,128>>>(x, DIMN, Wq, DIMN, qp, DIMN, DIMN, nullptr, nullptr, nullptr, 0.f, 0);
    l2norm_k<<<NTOK,256>>>(kp);
    l2norm_k<<<NTOK,256>>>(qp);

    for (int ch = 0; ch < NCH; ++ch) {
        const float* kt = kp + (size_t)ch*BC*DIMN;
        const float* vt = vp + (size_t)ch*BC*DIMN;
        const float* qt = qp + (size_t)ch*BC*DIMN;
        const float* w1c = (ch == 0) ? W1 : ((ch & 1) ? w1A : w1B);
        const float* w2c = (ch == 0) ? W2 : ((ch & 1) ? w2A : w2B);
        float* w1n = (ch & 1) ? w1B : w1A;
        float* w2n = (ch & 1) ? w2B : w2A;
        const float* gp3 = gch + ch*3;

        // 1) h1 = kt @ w1^T ; a1 = silu(h1)
        mgemm_k<32,64,true,true,1><<<dim3(HIDN/64, BC/32),128>>>(
            kt, DIMN, w1c, DIMN, h1, HIDN, DIMN, nullptr, a1, nullptr, 0.f, 0);
        // 2) d2 = scale * clip(a1 @ w2^T - v)
        mgemm_k<32,64,true,true,2><<<dim3(DIMN/64, BC/32),128>>>(
            a1, HIDN, w2c, HIDN, d2, DIMN, HIDN, vt, nullptr, nullptr, SCALE_CONST, 0);
        // 3) d1 = (d2 @ w2) * silu'(h1)     (B is [K=D, N=H] -> BKM=false)
        mgemm_k<32,64,true,false,3><<<dim3(HIDN/64, BC/32),128>>>(
            d2, DIMN, w2c, HIDN, d1, HIDN, DIMN, h1, nullptr, nullptr, 0.f, 0);
        // 4) w2 update: g2[d,h] = sum_bc d2^T a1 ; momentum/decay fused
        mgemm_k<64,64,false,false,4><<<dim3(HIDN/64, DIMN/64),128>>>(
            d2, DIMN, a1, HIDN, w2n, HIDN, BC, w2c, m2, gp3, 0.f, 0);
        // 5) w1 update: g1[h,d] = sum_bc d1^T kt
        mgemm_k<64,64,false,false,4><<<dim3(DIMN/64, HIDN/64),128>>>(
            d1, HIDN, kt, DIMN, w1n, DIMN, BC, w1c, m1, gp3, 0.f, 0);
        // 6) aq = silu(qt @ w1n^T)
        mgemm_k<32,64,true,true,5><<<dim3(HIDN/64, BC/32),128>>>(
            qt, DIMN, w1n, DIMN, aq, HIDN, DIMN, nullptr, nullptr, nullptr, 0.f, 0);
        // 7) y_chunk = aq @ w2n^T  -> natural [B,S,D] layout
        mgemm_k<32,64,true,true,6><<<dim3(DIMN/64, BC/32),128>>>(
            aq, HIDN, w2n, HIDN, y, DIMN, HIDN, nullptr, nullptr, nullptr, 0.f, ch*CHK);
    }

    // out = y @ Wout^T
    mgemm_k<64,64,true,true,0><<<dim3(DIMN/64, NTOK/64),128>>>(
        y, DIMN, Wout, DIMN, out, DIMN, DIMN, nullptr, nullptr, nullptr, 0.f, 0);
}

// round 4
// speedup vs baseline: 1.3985x; 1.1858x over previous
#include <cuda_runtime.h>
#include <cuda_bf16.h>
#include <math.h>

// ---------------- problem constants ----------------
#define DIMN 1024
#define HIDN 2048
#define BB   4
#define SS   2048
#define CHK  64
#define NCH  32        // SS/CHK
#define BC   256       // BB*CHK
#define NTOK 8192      // BB*SS
#define EPSN 1e-8f
#define SCALE_CONST (2.0f/(BB*CHK*DIMN))

using bf = __nv_bfloat16;

// ---------------- device scratch (no runtime allocs allowed) ----------------
// pre-split inputs
__device__ bf g_xh[NTOK*DIMN],  g_xl[NTOK*DIMN];
__device__ bf g_wkh[DIMN*DIMN], g_wkl[DIMN*DIMN];
__device__ bf g_wvh[DIMN*DIMN], g_wvl[DIMN*DIMN];
__device__ bf g_wqh[DIMN*DIMN], g_wql[DIMN*DIMN];
__device__ bf g_woh[DIMN*DIMN], g_wol[DIMN*DIMN];
// projections (fp32 staging for k/q before l2norm; v straight to hi/lo)
__device__ float g_kp[NCH*BC*DIMN];
__device__ float g_qp[NCH*BC*DIMN];
__device__ bf g_kph[NCH*BC*DIMN], g_kpl[NCH*BC*DIMN];
__device__ bf g_qph[NCH*BC*DIMN], g_qpl[NCH*BC*DIMN];
__device__ bf g_vph[NCH*BC*DIMN], g_vpl[NCH*BC*DIMN];
// scan intermediates
__device__ float g_h1[BC*HIDN];
__device__ bf g_a1h[BC*HIDN], g_a1l[BC*HIDN];
__device__ bf g_d2h[BC*DIMN], g_d2l[BC*DIMN];
__device__ bf g_d1h[BC*HIDN], g_d1l[BC*HIDN];
__device__ bf g_aqh[BC*HIDN], g_aql[BC*HIDN];
__device__ bf g_yh[NTOK*DIMN], g_yl[NTOK*DIMN];
// recurrent state: fp32 masters + hi/lo operand copies, ping-pong
__device__ float g_w1f[2][HIDN*DIMN];
__device__ bf    g_w1h[2][HIDN*DIMN], g_w1l[2][HIDN*DIMN];
__device__ float g_w2f[2][DIMN*HIDN];
__device__ bf    g_w2h[2][DIMN*HIDN], g_w2l[2][DIMN*HIDN];
__device__ float g_m1[HIDN*DIMN];
__device__ float g_m2[DIMN*HIDN];
__device__ float g_gate_tok[NTOK*3];
__device__ float g_gates[NCH*3];

// ---------------- math helpers ----------------
__device__ __forceinline__ float sigf(float x){ return 1.0f/(1.0f+expf(-x)); }
__device__ __forceinline__ float siluf(float x){ return x*sigf(x); }
__device__ __forceinline__ float siluderivf(float x){ float s=sigf(x); return s*(1.0f + x*(1.0f-s)); }
__device__ __forceinline__ float clip1f(float x){ return fminf(fmaxf(x,-1.0f),1.0f); }
__device__ __forceinline__ void store_hl(bf* H, bf* L, size_t idx, float v){
    bf h = __float2bfloat16_rn(v);
    H[idx] = h;
    L[idx] = __float2bfloat16_rn(v - __bfloat162float(h));
}

// ---------------- bf16 mma.sync core ----------------
__device__ __forceinline__ void mma_bf16(float* d, const unsigned* a, const unsigned* b){
    asm volatile(
        "mma.sync.aligned.m16n8k16.row.col.f32.bf16.bf16.f32 "
        "{%0,%1,%2,%3}, {%4,%5,%6,%7}, {%8,%9}, {%0,%1,%2,%3};\n"
        : "+f"(d[0]), "+f"(d[1]), "+f"(d[2]), "+f"(d[3])
        : "r"(a[0]), "r"(a[1]), "r"(a[2]), "r"(a[3]), "r"(b[0]), "r"(b[1]));
}

// ---------------- register-staged tile loader (double-buffer support) ----------------
// Loads a [R x KC] bf16 tile (hi + lo arrays). KM=true: source [rows][K] k-contig.
// KM=false: source [K][rows] r-contig (transpose on smem store).
template<int R, bool KM, int KC, int KS>
struct Loader {
    static constexpr int CH = (R*KC)/(128*8);   // 16B chunks per thread per array
    uint4 vh[CH], vl[CH];
    __device__ __forceinline__ void fetch(const bf* __restrict__ Ph, const bf* __restrict__ Pl,
                                          int ld, int r0, int k0, int tid){
        #pragma unroll
        for (int c = 0; c < CH; ++c){
            int id = tid + c*128;
            if constexpr (KM){
                int r = id/(KC/8), kq = (id%(KC/8))*8;
                size_t off = (size_t)(r0+r)*ld + k0 + kq;
                vh[c] = *(const uint4*)(Ph + off);
                vl[c] = *(const uint4*)(Pl + off);
            } else {
                int k = id/(R/8), rq = (id%(R/8))*8;
                size_t off = (size_t)(k0+k)*ld + r0 + rq;
                vh[c] = *(const uint4*)(Ph + off);
                vl[c] = *(const uint4*)(Pl + off);
            }
        }
    }
    __device__ __forceinline__ void store(bf* Sh, bf* Sl, int tid){
        #pragma unroll
        for (int c = 0; c < CH; ++c){
            int id = tid + c*128;
            if constexpr (KM){
                int r = id/(KC/8), kq = (id%(KC/8))*8;
                *(uint4*)(Sh + r*KS + kq) = vh[c];
                *(uint4*)(Sl + r*KS + kq) = vl[c];
            } else {
                int k = id/(R/8), rq = (id%(R/8))*8;
                const bf* ph = (const bf*)&vh[c];
                const bf* pl = (const bf*)&vl[c];
                #pragma unroll
                for (int j = 0; j < 8; ++j){
                    Sh[(rq+j)*KS + k] = ph[j];
                    Sl[(rq+j)*KS + k] = pl[j];
                }
            }
        }
    }
};

template<int BM,int BN,int KS>
struct SmemT {
    bf a[2][2][BM*KS];   // [buf][hi/lo]
    bf b[2][2][BN*KS];
};

// ---------------- tensor-core GEMM core: C[M,N] = sum_k A(m,k)*B(n,k) ----------------
// Epilogues:
//  0: C = acc (fp32)
//  1: C = acc (fp32 h1); Ch/Cl = silu(acc)  (a1)
//  2: Ch/Cl = scale * clip(acc - (x0h+x0l), +-1)         (d2)
//  3: Ch/Cl = acc * silu'(f0)                            (d1)
//  4: g=clip(acc); mn=eta*f1 - lr*g; f1=mn; w=(1-alpha)*f0+mn; C=w; Ch/Cl=w
//  5: Ch/Cl = silu(acc)                                  (aq)
//  6: Ch/Cl = acc at natural-layout row (chunk -> [B,S,D])   (y)
//  7: C = silu(acc) fp32 at chunk-permuted row           (k,q staging)
//  8: Ch/Cl = silu(acc) at chunk-permuted row            (v)
template<int BM,int BN,bool AKM,bool BKM,int EP>
__device__ __forceinline__ void mgemm_core(
    SmemT<BM,BN,40>& sm,
    const bf* __restrict__ Ah, const bf* __restrict__ Al, int lda,
    const bf* __restrict__ Bh, const bf* __restrict__ Bl, int ldb,
    float* __restrict__ C, bf* __restrict__ Ch, bf* __restrict__ Cl, int ldc,
    int K,
    const float* __restrict__ f0,
    const bf* __restrict__ x0h, const bf* __restrict__ x0l,
    float* __restrict__ f1,
    const float* __restrict__ gates,
    float scale, int base, int m0, int n0)
{
    constexpr int KC = 32;
    constexpr int KS = 40;
    constexpr int NI = (BM == 64) ? 4 : 2;

    const int tid  = threadIdx.x;
    const int lane = tid & 31;
    const int wid  = tid >> 5;
    const int g    = lane >> 2;
    const int tg   = lane & 3;
    const int wm = (BM == 64) ? (wid >> 1) * 32 : 0;
    const int wn = (BM == 64) ? (wid & 1) * 32 : wid * 16;

    float acc[2][NI][4] = {};

    Loader<BM,AKM,KC,KS> la;
    Loader<BN,BKM,KC,KS> lb;

    la.fetch(Ah, Al, lda, m0, 0, tid);
    lb.fetch(Bh, Bl, ldb, n0, 0, tid);
    la.store(sm.a[0][0], sm.a[0][1], tid);
    lb.store(sm.b[0][0], sm.b[0][1], tid);
    __syncthreads();

    int cur = 0;
    for (int k0 = 0; k0 < K; k0 += KC) {
        bool more = (k0 + KC) < K;
        if (more) {
            la.fetch(Ah, Al, lda, m0, k0 + KC, tid);
            lb.fetch(Bh, Bl, ldb, n0, k0 + KC, tid);
        }
        const bf* Ahs = sm.a[cur][0]; const bf* Als = sm.a[cur][1];
        const bf* Bhs = sm.b[cur][0]; const bf* Bls = sm.b[cur][1];

        #pragma unroll
        for (int kt = 0; kt < KC; kt += 16) {
            unsigned ah[2][4], al_[2][4], bh[NI][2], bl[NI][2];
            #pragma unroll
            for (int mi = 0; mi < 2; ++mi) {
                int o = (wm + mi*16 + g)*KS + kt + tg*2;
                ah[mi][0] = *(const unsigned*)(Ahs + o);
                ah[mi][1] = *(const unsigned*)(Ahs + o + 8*KS);
                ah[mi][2] = *(const unsigned*)(Ahs + o + 8);
                ah[mi][3] = *(const unsigned*)(Ahs + o + 8*KS + 8);
                al_[mi][0] = *(const unsigned*)(Als + o);
                al_[mi][1] = *(const unsigned*)(Als + o + 8*KS);
                al_[mi][2] = *(const unsigned*)(Als + o + 8);
                al_[mi][3] = *(const unsigned*)(Als + o + 8*KS + 8);
            }
            #pragma unroll
            for (int ni = 0; ni < NI; ++ni) {
                int o = (wn + ni*8 + g)*KS + kt + tg*2;
                bh[ni][0] = *(const unsigned*)(Bhs + o);
                bh[ni][1] = *(const unsigned*)(Bhs + o + 8);
                bl[ni][0] = *(const unsigned*)(Bls + o);
                bl[ni][1] = *(const unsigned*)(Bls + o + 8);
            }
            #pragma unroll
            for (int mi = 0; mi < 2; ++mi)
                #pragma unroll
                for (int ni = 0; ni < NI; ++ni) {
                    mma_bf16(acc[mi][ni], ah[mi],  bh[ni]);   // hi*hi
                    mma_bf16(acc[mi][ni], ah[mi],  bl[ni]);   // hi*lo
                    mma_bf16(acc[mi][ni], al_[mi], bh[ni]);   // lo*hi
                }
        }

        if (more) {
            la.store(sm.a[cur^1][0], sm.a[cur^1][1], tid);
            lb.store(sm.b[cur^1][0], sm.b[cur^1][1], tid);
            __syncthreads();
            cur ^= 1;
        }
    }

    // ---- epilogue ----
    float lrg = 0.f, alg = 0.f, etg = 0.f;
    if constexpr (EP == 4) { lrg = gates[0]; alg = gates[1]; etg = gates[2]; }

    #pragma unroll
    for (int mi = 0; mi < 2; ++mi)
    #pragma unroll
    for (int rr = 0; rr < 2; ++rr) {
        int m = m0 + wm + mi*16 + rr*8 + g;
        size_t crow;
        if constexpr (EP == 6) {                 // chunk -> natural [B,S,D]
            int b = m >> 6, ci = m & 63;
            crow = (size_t)(b*SS + base + ci) * ldc;
        } else if constexpr (EP == 7 || EP == 8) { // token -> chunk-permuted
            int b = m >> 11, s = m & (SS-1);
            crow = (size_t)((s >> 6)*BC + b*CHK + (s & 63)) * ldc;
        } else {
            crow = (size_t)m * ldc;
        }
        size_t srow = (size_t)m * ldc;
        #pragma unroll
        for (int ni = 0; ni < NI; ++ni) {
            int n = n0 + wn + ni*8 + tg*2;
            #pragma unroll
            for (int cc = 0; cc < 2; ++cc) {
                float v = acc[mi][ni][rr*2 + cc];
                size_t idx  = crow + n + cc;
                size_t sidx = srow + n + cc;
                if constexpr (EP == 0) C[idx] = v;
                else if constexpr (EP == 1) { C[idx] = v; store_hl(Ch, Cl, idx, siluf(v)); }
                else if constexpr (EP == 2) {
                    float vv = __bfloat162float(x0h[sidx]) + __bfloat162float(x0l[sidx]);
                    store_hl(Ch, Cl, idx, scale * clip1f(v - vv));
                }
                else if constexpr (EP == 3) store_hl(Ch, Cl, idx, v * siluderivf(f0[sidx]));
                else if constexpr (EP == 4) {
                    float gg = clip1f(v);
                    float mn = etg * f1[idx] - lrg * gg;
                    f1[idx] = mn;
                    float w = (1.0f - alg) * f0[idx] + mn;
                    C[idx] = w;
                    store_hl(Ch, Cl, idx, w);
                }
                else if constexpr (EP == 5) store_hl(Ch, Cl, idx, siluf(v));
                else if constexpr (EP == 6) store_hl(Ch, Cl, idx, v);
                else if constexpr (EP == 7) C[idx] = siluf(v);
                else if constexpr (EP == 8) store_hl(Ch, Cl, idx, siluf(v));
            }
        }
    }
}

template<int BM,int BN,bool AKM,bool BKM,int EP>
__global__ __launch_bounds__(128,3)
void mgemm_k(const bf* __restrict__ Ah, const bf* __restrict__ Al, int lda,
             const bf* __restrict__ Bh, const bf* __restrict__ Bl, int ldb,
             float* __restrict__ C, bf* __restrict__ Ch, bf* __restrict__ Cl, int ldc,
             int K,
             const float* __restrict__ f0,
             const bf* __restrict__ x0h, const bf* __restrict__ x0l,
             float* __restrict__ f1,
             const float* __restrict__ gates, float scale, int base)
{
    __shared__ SmemT<BM,BN,40> sm;
    mgemm_core<BM,BN,AKM,BKM,EP>(sm, Ah,Al,lda, Bh,Bl,ldb, C,Ch,Cl,ldc, K,
                                 f0,x0h,x0l,f1, gates, scale, base,
                                 blockIdx.y*BM, blockIdx.x*BN);
}

// fused weight updates (w2 grad + w1 grad), both EP4, 64x64 tiles, K=BC
__global__ __launch_bounds__(128,3)
void wupd_k(const bf* __restrict__ d2h, const bf* __restrict__ d2l,
            const bf* __restrict__ a1h, const bf* __restrict__ a1l,
            float* __restrict__ w2n, bf* __restrict__ w2nh, bf* __restrict__ w2nl,
            const float* __restrict__ w2o, float* __restrict__ m2,
            const bf* __restrict__ d1h, const bf* __restrict__ d1l,
            const bf* __restrict__ kth, const bf* __restrict__ ktl,
            float* __restrict__ w1n, bf* __restrict__ w1nh, bf* __restrict__ w1nl,
            const float* __restrict__ w1o, float* __restrict__ m1,
            const float* __restrict__ gates)
{
    __shared__ SmemT<64,64,40> sm;
    int bx = blockIdx.x;
    constexpr int T2 = (HIDN/64)*(DIMN/64);   // 512 tiles for w2 [DIMN x HIDN]
    if (bx < T2) {
        int nt = bx % (HIDN/64), mt = bx / (HIDN/64);
        mgemm_core<64,64,false,false,4>(sm, d2h,d2l,DIMN, a1h,a1l,HIDN,
                                        w2n,w2nh,w2nl,HIDN, BC,
                                        w2o,nullptr,nullptr,m2, gates, 0.f, 0,
                                        mt*64, nt*64);
    } else {
        int i = bx - T2;
        int nt = i % (DIMN/64), mt = i / (DIMN/64);
        mgemm_core<64,64,false,false,4>(sm, d1h,d1l,HIDN, kth,ktl,DIMN,
                                        w1n,w1nh,w1nl,DIMN, BC,
                                        w1o,nullptr,nullptr,m1, gates, 0.f, 0,
                                        mt*64, nt*64);
    }
}

// ---------------- fp32 -> bf16 hi/lo pre-split ----------------
__global__ void split_k(const float* __restrict__ s, bf* __restrict__ h, bf* __restrict__ l, int n)
{
    int i = (blockIdx.x*256 + threadIdx.x)*4;
    if (i >= n) return;
    float4 v = *(const float4*)(s + i);
    float f[4] = {v.x, v.y, v.z, v.w};
    bf hv[4], lv[4];
    #pragma unroll
    for (int j = 0; j < 4; ++j) {
        hv[j] = __float2bfloat16_rn(f[j]);
        lv[j] = __float2bfloat16_rn(f[j] - __bfloat162float(hv[j]));
    }
    *(uint2*)(h + i) = *(uint2*)hv;
    *(uint2*)(l + i) = *(uint2*)lv;
}

// ---------------- l2 normalize fp32 row -> hi/lo bf16, D=1024, block=256 ----------------
__global__ void l2norm_k(const float* __restrict__ src, bf* __restrict__ h, bf* __restrict__ l)
{
    int row = blockIdx.x;
    const float* r = src + (size_t)row * DIMN;
    int t = threadIdx.x;
    float4 v = *(const float4*)(r + t*4);
    float ss = v.x*v.x + v.y*v.y + v.z*v.z + v.w*v.w;
    __shared__ float red[256];
    red[t] = ss; __syncthreads();
    for (int o = 128; o > 0; o >>= 1) { if (t < o) red[t] += red[t+o]; __syncthreads(); }
    float inv = rsqrtf(red[0] + EPSN);
    float f[4] = {v.x*inv, v.y*inv, v.z*inv, v.w*inv};
    bf hv[4], lv[4];
    #pragma unroll
    for (int j = 0; j < 4; ++j) {
        hv[j] = __float2bfloat16_rn(f[j]);
        lv[j] = __float2bfloat16_rn(f[j] - __bfloat162float(hv[j]));
    }
    size_t o4 = (size_t)row * DIMN + t*4;
    *(uint2*)(h + o4) = *(uint2*)hv;
    *(uint2*)(l + o4) = *(uint2*)lv;
}

// ---------------- per-token gate dots: sigmoid(x . w + b), 3 gates ----------------
__global__ void gate_tok_k(const float* __restrict__ x,
                           const float* __restrict__ wlr,  const float* __restrict__ blr,
                           const float* __restrict__ wdec, const float* __restrict__ bdec,
                           const float* __restrict__ wmom, const float* __restrict__ bmom)
{
    int tok = blockIdx.x;
    int t = threadIdx.x;   // 256
    const float* xr = x + (size_t)tok * DIMN;
    float s0 = 0.f, s1 = 0.f, s2 = 0.f;
    for (int i = t; i < DIMN; i += 256) {
        float xi = xr[i];
        s0 += xi * wlr[i]; s1 += xi * wdec[i]; s2 += xi * wmom[i];
    }
    __shared__ float r0[256], r1[256], r2[256];
    r0[t] = s0; r1[t] = s1; r2[t] = s2; __syncthreads();
    for (int o = 128; o > 0; o >>= 1) {
        if (t < o) { r0[t] += r0[t+o]; r1[t] += r1[t+o]; r2[t] += r2[t+o]; }
        __syncthreads();
    }
    if (t == 0) {
        g_gate_tok[tok*3+0] = sigf(r0[0] + blr[0]);
        g_gate_tok[tok*3+1] = sigf(r1[0] + bdec[0]);
        g_gate_tok[tok*3+2] = sigf(r2[0] + bmom[0]);
    }
}

// ---------------- per-chunk gate means ----------------
__global__ void gate_chunk_k()
{
    int ch = blockIdx.x;
    int t = threadIdx.x;   // 256
    int b = t >> 6, ci = t & 63;
    int tok = b*SS + ch*CHK + ci;
    __shared__ float r0[256], r1[256], r2[256];
    r0[t] = g_gate_tok[tok*3+0];
    r1[t] = g_gate_tok[tok*3+1];
    r2[t] = g_gate_tok[tok*3+2];
    __syncthreads();
    for (int o = 128; o > 0; o >>= 1) {
        if (t < o) { r0[t] += r0[t+o]; r1[t] += r1[t+o]; r2[t] += r2[t+o]; }
        __syncthreads();
    }
    if (t == 0) {
        g_gates[ch*3+0] = r0[0] * (1.0f/BC);
        g_gates[ch*3+1] = r1[0] * (1.0f/BC);
        g_gates[ch*3+2] = r2[0] * (1.0f/BC);
    }
}

// ---------------- host orchestration ----------------
extern "C" void kernel_launch(void* const* d_in, const int* in_sizes, int n_in,
                              void* d_out, int out_size)
{
    const float* x    = (const float*)d_in[0];
    const float* Wk   = (const float*)d_in[1];
    const float* Wv   = (const float*)d_in[2];
    const float* Wq   = (const float*)d_in[3];
    const float* Wout = (const float*)d_in[4];
    const float* W1   = (const float*)d_in[5];
    const float* W2   = (const float*)d_in[6];
    const float* Wlr  = (const float*)d_in[7];
    const float* blr  = (const float*)d_in[8];
    const float* Wdec = (const float*)d_in[9];
    const float* bdec = (const float*)d_in[10];
    const float* Wmom = (const float*)d_in[11];
    const float* bmom = (const float*)d_in[12];
    float* out = (float*)d_out;

    // resolve device-global addresses
    bf *xh,*xl,*wkh,*wkl,*wvh,*wvl,*wqh,*wql,*woh,*wol;
    bf *kph,*kpl,*qph,*qpl,*vph,*vpl;
    bf *a1h,*a1l,*d2h,*d2l,*d1h,*d1l,*aqh,*aql,*yh,*yl;
    float *kp,*qp,*h1,*m1,*m2,*gch;
    float *w1f0,*w1f1,*w2f0,*w2f1;
    bf *w1h0,*w1h1,*w1l0,*w1l1,*w2h0,*w2h1,*w2l0,*w2l1;

    cudaGetSymbolAddress((void**)&xh, g_xh);   cudaGetSymbolAddress((void**)&xl, g_xl);
    cudaGetSymbolAddress((void**)&wkh,g_wkh);  cudaGetSymbolAddress((void**)&wkl,g_wkl);
    cudaGetSymbolAddress((void**)&wvh,g_wvh);  cudaGetSymbolAddress((void**)&wvl,g_wvl);
    cudaGetSymbolAddress((void**)&wqh,g_wqh);  cudaGetSymbolAddress((void**)&wql,g_wql);
    cudaGetSymbolAddress((void**)&woh,g_woh);  cudaGetSymbolAddress((void**)&wol,g_wol);
    cudaGetSymbolAddress((void**)&kp, g_kp);   cudaGetSymbolAddress((void**)&qp, g_qp);
    cudaGetSymbolAddress((void**)&kph,g_kph);  cudaGetSymbolAddress((void**)&kpl,g_kpl);
    cudaGetSymbolAddress((void**)&qph,g_qph);  cudaGetSymbolAddress((void**)&qpl,g_qpl);
    cudaGetSymbolAddress((void**)&vph,g_vph);  cudaGetSymbolAddress((void**)&vpl,g_vpl);
    cudaGetSymbolAddress((void**)&h1, g_h1);
    cudaGetSymbolAddress((void**)&a1h,g_a1h);  cudaGetSymbolAddress((void**)&a1l,g_a1l);
    cudaGetSymbolAddress((void**)&d2h,g_d2h);  cudaGetSymbolAddress((void**)&d2l,g_d2l);
    cudaGetSymbolAddress((void**)&d1h,g_d1h);  cudaGetSymbolAddress((void**)&d1l,g_d1l);
    cudaGetSymbolAddress((void**)&aqh,g_aqh);  cudaGetSymbolAddress((void**)&aql,g_aql);
    cudaGetSymbolAddress((void**)&yh, g_yh);   cudaGetSymbolAddress((void**)&yl, g_yl);
    cudaGetSymbolAddress((void**)&m1, g_m1);   cudaGetSymbolAddress((void**)&m2, g_m2);
    cudaGetSymbolAddress((void**)&gch,g_gates);
    { void* p;
      cudaGetSymbolAddress(&p, g_w1f); w1f0=(float*)p; w1f1=w1f0+HIDN*DIMN;
      cudaGetSymbolAddress(&p, g_w1h); w1h0=(bf*)p;    w1h1=w1h0+HIDN*DIMN;
      cudaGetSymbolAddress(&p, g_w1l); w1l0=(bf*)p;    w1l1=w1l0+HIDN*DIMN;
      cudaGetSymbolAddress(&p, g_w2f); w2f0=(float*)p; w2f1=w2f0+DIMN*HIDN;
      cudaGetSymbolAddress(&p, g_w2h); w2h0=(bf*)p;    w2h1=w2h0+DIMN*HIDN;
      cudaGetSymbolAddress(&p, g_w2l); w2l0=(bf*)p;    w2l1=w2l0+DIMN*HIDN;
    }

    // zero momentum each call (deterministic)
    cudaMemsetAsync(m1, 0, sizeof(float)*HIDN*DIMN);
    cudaMemsetAsync(m2, 0, sizeof(float)*DIMN*HIDN);

    // pre-split inputs to bf16 hi/lo
    split_k<<<(NTOK*DIMN)/1024, 256>>>(x,    xh,  xl,  NTOK*DIMN);
    split_k<<<(DIMN*DIMN)/1024, 256>>>(Wk,   wkh, wkl, DIMN*DIMN);
    split_k<<<(DIMN*DIMN)/1024, 256>>>(Wv,   wvh, wvl, DIMN*DIMN);
    split_k<<<(DIMN*DIMN)/1024, 256>>>(Wq,   wqh, wql, DIMN*DIMN);
    split_k<<<(DIMN*DIMN)/1024, 256>>>(Wout, woh, wol, DIMN*DIMN);
    split_k<<<(HIDN*DIMN)/1024, 256>>>(W1,   w1h1, w1l1, HIDN*DIMN);   // slot 1 = read slot for ch=0
    split_k<<<(DIMN*HIDN)/1024, 256>>>(W2,   w2h1, w2l1, DIMN*HIDN);

    // gates
    gate_tok_k<<<NTOK, 256>>>(x, Wlr, blr, Wdec, bdec, Wmom, bmom);
    gate_chunk_k<<<NCH, 256>>>();

    // projections: k,q -> fp32 staging (EP7) then l2norm->hi/lo; v -> hi/lo (EP8)
    dim3 gproj(DIMN/64, NTOK/64);
    mgemm_k<64,64,true,true,7><<<gproj,128>>>(xh,xl,DIMN, wkh,wkl,DIMN, kp,nullptr,nullptr,DIMN, DIMN, nullptr,nullptr,nullptr,nullptr, nullptr,0.f,0);
    mgemm_k<64,64,true,true,7><<<gproj,128>>>(xh,xl,DIMN, wqh,wql,DIMN, qp,nullptr,nullptr,DIMN, DIMN, nullptr,nullptr,nullptr,nullptr, nullptr,0.f,0);
    mgemm_k<64,64,true,true,8><<<gproj,128>>>(xh,xl,DIMN, wvh,wvl,DIMN, nullptr,vph,vpl,DIMN, DIMN, nullptr,nullptr,nullptr,nullptr, nullptr,0.f,0);
    l2norm_k<<<NTOK,256>>>(kp, kph, kpl);
    l2norm_k<<<NTOK,256>>>(qp, qph, qpl);

    for (int ch = 0; ch < NCH; ++ch) {
        size_t co = (size_t)ch*BC*DIMN;
        const bf *kth = kph+co, *ktl = kpl+co;
        const bf *qth = qph+co, *qtl = qpl+co;
        const bf *vth = vph+co, *vtl = vpl+co;
        int wi = ch & 1;                 // write slot
        int ri = 1 - wi;                 // read slot (ch=0 reads slot 1 = pre-split W1/W2)
        const float* w1o = (ch == 0) ? W1 : (ri ? w1f1 : w1f0);
        const float* w2o = (ch == 0) ? W2 : (ri ? w2f1 : w2f0);
        const bf *w1rh = ri ? w1h1 : w1h0, *w1rl = ri ? w1l1 : w1l0;
        const bf *w2rh = ri ? w2h1 : w2h0, *w2rl = ri ? w2l1 : w2l0;
        float* w1n = wi ? w1f1 : w1f0;
        float* w2n = wi ? w2f1 : w2f0;
        bf *w1nh = wi ? w1h1 : w1h0, *w1nl = wi ? w1l1 : w1l0;
        bf *w2nh = wi ? w2h1 : w2h0, *w2nl = wi ? w2l1 : w2l0;
        const float* gp3 = gch + ch*3;

        // 1) h1 = kt @ w1^T (fp32) ; a1 = silu(h1) (hi/lo)
        mgemm_k<32,64,true,true,1><<<dim3(HIDN/64, BC/32),128>>>(
            kth,ktl,DIMN, w1rh,w1rl,DIMN, h1,a1h,a1l,HIDN, DIMN,
            nullptr,nullptr,nullptr,nullptr, nullptr,0.f,0);
        // 2) d2 = scale * clip(a1 @ w2^T - v)
        mgemm_k<32,64,true,true,2><<<dim3(DIMN/64, BC/32),128>>>(
            a1h,a1l,HIDN, w2rh,w2rl,HIDN, nullptr,d2h,d2l,DIMN, HIDN,
            nullptr,vth,vtl,nullptr, nullptr,SCALE_CONST,0);
        // 3) d1 = (d2 @ w2) * silu'(h1)
        mgemm_k<32,64,true,false,3><<<dim3(HIDN/64, BC/32),128>>>(
            d2h,d2l,DIMN, w2rh,w2rl,HIDN, nullptr,d1h,d1l,HIDN, DIMN,
            h1,nullptr,nullptr,nullptr, nullptr,0.f,0);
        // 4+5) fused weight updates
        wupd_k<<<(HIDN/64)*(DIMN/64)*2,128>>>(
            d2h,d2l, a1h,a1l, w2n,w2nh,w2nl, w2o,m2,
            d1h,d1l, kth,ktl, w1n,w1nh,w1nl, w1o,m1, gp3);
        // 6) aq = silu(qt @ w1n^T)
        mgemm_k<32,64,true,true,5><<<dim3(HIDN/64, BC/32),128>>>(
            qth,qtl,DIMN, w1nh,w1nl,DIMN, nullptr,aqh,aql,HIDN, DIMN,
            nullptr,nullptr,nullptr,nullptr, nullptr,0.f,0);
        // 7) y_chunk = aq @ w2n^T -> natural layout (hi/lo)
        mgemm_k<32,64,true,true,6><<<dim3(DIMN/64, BC/32),128>>>(
            aqh,aql,HIDN, w2nh,w2nl,HIDN, nullptr,yh,yl,DIMN, HIDN,
            nullptr,nullptr,nullptr,nullptr, nullptr,0.f,ch*CHK);
    }

    // out = y @ Wout^T (fp32)
    mgemm_k<64,64,true,true,0><<<dim3(DIMN/64, NTOK/64),128>>>(
        yh,yl,DIMN, woh,wol,DIMN, out,nullptr,nullptr,DIMN, DIMN,
        nullptr,nullptr,nullptr,nullptr, nullptr,0.f,0);
}

// round 5
// speedup vs baseline: 1.4425x; 1.0315x over previous
#include <cuda_runtime.h>
#include <cuda_bf16.h>
#include <math.h>

// ---------------- problem constants ----------------
#define DIMN 1024
#define HIDN 2048
#define BB   4
#define SS   2048
#define CHK  64
#define NCH  32        // SS/CHK
#define BC   256       // BB*CHK
#define NTOK 8192      // BB*SS
#define EPSN 1e-8f
#define SCALE_CONST (2.0f/(BB*CHK*DIMN))

using bf = __nv_bfloat16;

// ---------------- device scratch (no runtime allocs allowed) ----------------
__device__ bf g_xh[NTOK*DIMN],  g_xl[NTOK*DIMN];
__device__ bf g_wkh[DIMN*DIMN], g_wkl[DIMN*DIMN];
__device__ bf g_wvh[DIMN*DIMN], g_wvl[DIMN*DIMN];
__device__ bf g_wqh[DIMN*DIMN], g_wql[DIMN*DIMN];
__device__ bf g_woh[DIMN*DIMN], g_wol[DIMN*DIMN];
__device__ float g_kp[NCH*BC*DIMN];
__device__ float g_qp[NCH*BC*DIMN];
__device__ bf g_kph[NCH*BC*DIMN], g_kpl[NCH*BC*DIMN];
__device__ bf g_qph[NCH*BC*DIMN], g_qpl[NCH*BC*DIMN];
__device__ bf g_vph[NCH*BC*DIMN], g_vpl[NCH*BC*DIMN];
__device__ float g_h1[BC*HIDN];
__device__ bf g_a1h[BC*HIDN], g_a1l[BC*HIDN];
__device__ bf g_d2h[BC*DIMN], g_d2l[BC*DIMN];
__device__ bf g_d1h[BC*HIDN], g_d1l[BC*HIDN];
__device__ bf g_aqh[BC*HIDN], g_aql[BC*HIDN];
__device__ bf g_yh[NTOK*DIMN], g_yl[NTOK*DIMN];
__device__ float g_w1f[2][HIDN*DIMN];
__device__ bf    g_w1h[2][HIDN*DIMN], g_w1l[2][HIDN*DIMN];
__device__ float g_w2f[2][DIMN*HIDN];
__device__ bf    g_w2h[2][DIMN*HIDN], g_w2l[2][DIMN*HIDN];
__device__ float g_m1[HIDN*DIMN];
__device__ float g_m2[DIMN*HIDN];
__device__ float g_gate_tok[NTOK*3];
__device__ float g_gates[NCH*3];

// ---------------- math helpers ----------------
__device__ __forceinline__ float sigf(float x){ return 1.0f/(1.0f+expf(-x)); }
__device__ __forceinline__ float siluf(float x){ return x*sigf(x); }
__device__ __forceinline__ float siluderivf(float x){ float s=sigf(x); return s*(1.0f + x*(1.0f-s)); }
__device__ __forceinline__ float clip1f(float x){ return fminf(fmaxf(x,-1.0f),1.0f); }
__device__ __forceinline__ void store_hl(bf* H, bf* L, size_t idx, float v){
    bf h = __float2bfloat16_rn(v);
    H[idx] = h;
    L[idx] = __float2bfloat16_rn(v - __bfloat162float(h));
}

// ---------------- bf16 mma.sync + cp.async primitives ----------------
__device__ __forceinline__ void mma_bf16(float* d, const unsigned* a, const unsigned* b){
    asm volatile(
        "mma.sync.aligned.m16n8k16.row.col.f32.bf16.bf16.f32 "
        "{%0,%1,%2,%3}, {%4,%5,%6,%7}, {%8,%9}, {%0,%1,%2,%3};\n"
        : "+f"(d[0]), "+f"(d[1]), "+f"(d[2]), "+f"(d[3])
        : "r"(a[0]), "r"(a[1]), "r"(a[2]), "r"(a[3]), "r"(b[0]), "r"(b[1]));
}
__device__ __forceinline__ void cpa16(bf* s, const bf* g){
    unsigned sa = (unsigned)__cvta_generic_to_shared(s);
    asm volatile("cp.async.cg.shared.global [%0], [%1], 16;\n" :: "r"(sa), "l"(g));
}
__device__ __forceinline__ void cp_commit(){ asm volatile("cp.async.commit_group;\n"); }
template<int N> __device__ __forceinline__ void cp_wait(){ asm volatile("cp.async.wait_group %0;\n" :: "n"(N)); }

// ---------------- register-staged loader (KM=false transpose path) ----------------
template<int R, bool KM, int KC, int KS>
struct Loader {
    static constexpr int CH = (R*KC)/(128*8);
    uint4 vh[CH], vl[CH];
    __device__ __forceinline__ void fetch(const bf* __restrict__ Ph, const bf* __restrict__ Pl,
                                          int ld, int r0, int k0, int tid){
        #pragma unroll
        for (int c = 0; c < CH; ++c){
            int id = tid + c*128;
            if constexpr (KM){
                int r = id/(KC/8), kq = (id%(KC/8))*8;
                size_t off = (size_t)(r0+r)*ld + k0 + kq;
                vh[c] = *(const uint4*)(Ph + off);
                vl[c] = *(const uint4*)(Pl + off);
            } else {
                int k = id/(R/8), rq = (id%(R/8))*8;
                size_t off = (size_t)(k0+k)*ld + r0 + rq;
                vh[c] = *(const uint4*)(Ph + off);
                vl[c] = *(const uint4*)(Pl + off);
            }
        }
    }
    __device__ __forceinline__ void store(bf* Sh, bf* Sl, int tid){
        #pragma unroll
        for (int c = 0; c < CH; ++c){
            int id = tid + c*128;
            if constexpr (KM){
                int r = id/(KC/8), kq = (id%(KC/8))*8;
                *(uint4*)(Sh + r*KS + kq) = vh[c];
                *(uint4*)(Sl + r*KS + kq) = vl[c];
            } else {
                int k = id/(R/8), rq = (id%(R/8))*8;
                const bf* ph = (const bf*)&vh[c];
                const bf* pl = (const bf*)&vl[c];
                #pragma unroll
                for (int j = 0; j < 8; ++j){
                    Sh[(rq+j)*KS + k] = ph[j];
                    Sl[(rq+j)*KS + k] = pl[j];
                }
            }
        }
    }
};

// ---------------- GEMM core: C[M,N] = sum_k A(m,k)*B(n,k) ----------------
// EP: 0 C=acc | 1 C=acc,Ch/Cl=silu | 2 Ch/Cl=scale*clip(acc-(x0h+x0l)) | 3 Ch/Cl=acc*silu'(f0)
//     4 weight update | 5 Ch/Cl=silu | 6 Ch/Cl=acc natural-layout | 7 C=silu perm | 8 Ch/Cl=silu perm
template<int BM,int BN,bool AKM,bool BKM,int EP>
__device__ __forceinline__ void mgemm_core(
    char* dsm,
    const bf* __restrict__ Ah, const bf* __restrict__ Al, int lda,
    const bf* __restrict__ Bh, const bf* __restrict__ Bl, int ldb,
    float* __restrict__ C, bf* __restrict__ Ch, bf* __restrict__ Cl, int ldc,
    int K,
    const float* __restrict__ f0,
    const bf* __restrict__ x0h, const bf* __restrict__ x0l,
    float* __restrict__ f1,
    const float* __restrict__ gates,
    float scale, int base, int m0, int n0)
{
    constexpr int KC = 32;
    constexpr int KS = 40;
    constexpr int NI = (BM == 64) ? 4 : 2;
    constexpr int ASZ = BM*KS, BSZ = BN*KS;
    constexpr int STRIDE = 2*ASZ + 2*BSZ;

    const int tid  = threadIdx.x;
    const int lane = tid & 31;
    const int wid  = tid >> 5;
    const int g    = lane >> 2;
    const int tg   = lane & 3;
    const int wm = (BM == 64) ? (wid >> 1) * 32 : 0;
    const int wn = (BM == 64) ? (wid & 1) * 32 : wid * 16;

    bf* base_s = (bf*)dsm;

    float accm[2][NI][4] = {};
    float accc[2][NI][4] = {};

    auto compute_tile = [&](const bf* Ahs, const bf* Als, const bf* Bhs, const bf* Bls){
        #pragma unroll
        for (int kt = 0; kt < KC; kt += 16) {
            unsigned ah[2][4], al_[2][4], bh[NI][2], bl[NI][2];
            #pragma unroll
            for (int mi = 0; mi < 2; ++mi) {
                int o = (wm + mi*16 + g)*KS + kt + tg*2;
                ah[mi][0] = *(const unsigned*)(Ahs + o);
                ah[mi][1] = *(const unsigned*)(Ahs + o + 8*KS);
                ah[mi][2] = *(const unsigned*)(Ahs + o + 8);
                ah[mi][3] = *(const unsigned*)(Ahs + o + 8*KS + 8);
                al_[mi][0] = *(const unsigned*)(Als + o);
                al_[mi][1] = *(const unsigned*)(Als + o + 8*KS);
                al_[mi][2] = *(const unsigned*)(Als + o + 8);
                al_[mi][3] = *(const unsigned*)(Als + o + 8*KS + 8);
            }
            #pragma unroll
            for (int ni = 0; ni < NI; ++ni) {
                int o = (wn + ni*8 + g)*KS + kt + tg*2;
                bh[ni][0] = *(const unsigned*)(Bhs + o);
                bh[ni][1] = *(const unsigned*)(Bhs + o + 8);
                bl[ni][0] = *(const unsigned*)(Bls + o);
                bl[ni][1] = *(const unsigned*)(Bls + o + 8);
            }
            #pragma unroll
            for (int mi = 0; mi < 2; ++mi)
                #pragma unroll
                for (int ni = 0; ni < NI; ++ni) {
                    mma_bf16(accm[mi][ni], ah[mi],  bh[ni]);   // hi*hi  (chain 1)
                    mma_bf16(accc[mi][ni], ah[mi],  bl[ni]);   // hi*lo  (chain 2)
                    mma_bf16(accc[mi][ni], al_[mi], bh[ni]);   // lo*hi
                }
        }
    };

    if constexpr (AKM && BKM) {
        // ---- 4-stage cp.async pipeline ----
        constexpr int STG = 4;
        const int KT = K / KC;
        auto issue = [&](int s, int k0){
            bf* dAh = base_s + s*STRIDE; bf* dAl = dAh + ASZ;
            bf* dBh = dAl + ASZ;         bf* dBl = dBh + BSZ;
            #pragma unroll
            for (int c2 = 0; c2 < (BM*4)/128; ++c2){
                int id = tid + c2*128; int r = id >> 2, kq = (id & 3)*8;
                size_t off = (size_t)(m0+r)*lda + k0 + kq;
                cpa16(dAh + r*KS + kq, Ah + off);
                cpa16(dAl + r*KS + kq, Al + off);
            }
            #pragma unroll
            for (int c2 = 0; c2 < (BN*4)/128; ++c2){
                int id = tid + c2*128; int r = id >> 2, kq = (id & 3)*8;
                size_t off = (size_t)(n0+r)*ldb + k0 + kq;
                cpa16(dBh + r*KS + kq, Bh + off);
                cpa16(dBl + r*KS + kq, Bl + off);
            }
            cp_commit();
        };
        int fetch = 0;
        for (; fetch < STG-1 && fetch < KT; ++fetch) issue(fetch, fetch*KC);
        for (int c = 0; c < KT; ++c){
            cp_wait<STG-2>();
            __syncthreads();
            if (fetch < KT){ issue(fetch % STG, fetch*KC); ++fetch; }
            int s = c % STG;
            bf* pAh = base_s + s*STRIDE; bf* pAl = pAh + ASZ;
            bf* pBh = pAl + ASZ;         bf* pBl = pBh + BSZ;
            compute_tile(pAh, pAl, pBh, pBl);
        }
    } else {
        // ---- register-staged 2-buffer path (handles transpose loads) ----
        Loader<BM,AKM,KC,KS> la;
        Loader<BN,BKM,KC,KS> lb;
        bf* A0[2]; bf* A1[2]; bf* B0[2]; bf* B1[2];
        #pragma unroll
        for (int b = 0; b < 2; ++b){
            bf* p = base_s + b*STRIDE;
            A0[b] = p; A1[b] = p + ASZ; B0[b] = p + 2*ASZ; B1[b] = p + 2*ASZ + BSZ;
        }
        la.fetch(Ah, Al, lda, m0, 0, tid);
        lb.fetch(Bh, Bl, ldb, n0, 0, tid);
        la.store(A0[0], A1[0], tid);
        lb.store(B0[0], B1[0], tid);
        __syncthreads();
        int cur = 0;
        for (int k0 = 0; k0 < K; k0 += KC) {
            bool more = (k0 + KC) < K;
            if (more) {
                la.fetch(Ah, Al, lda, m0, k0 + KC, tid);
                lb.fetch(Bh, Bl, ldb, n0, k0 + KC, tid);
            }
            compute_tile(A0[cur], A1[cur], B0[cur], B1[cur]);
            if (more) {
                la.store(A0[cur^1], A1[cur^1], tid);
                lb.store(B0[cur^1], B1[cur^1], tid);
                __syncthreads();
                cur ^= 1;
            }
        }
    }

    // ---- epilogue ----
    float lrg = 0.f, alg = 0.f, etg = 0.f;
    if constexpr (EP == 4) { lrg = gates[0]; alg = gates[1]; etg = gates[2]; }

    #pragma unroll
    for (int mi = 0; mi < 2; ++mi)
    #pragma unroll
    for (int rr = 0; rr < 2; ++rr) {
        int m = m0 + wm + mi*16 + rr*8 + g;
        size_t crow;
        if constexpr (EP == 6) {
            int b = m >> 6, ci = m & 63;
            crow = (size_t)(b*SS + base + ci) * ldc;
        } else if constexpr (EP == 7 || EP == 8) {
            int b = m >> 11, s = m & (SS-1);
            crow = (size_t)((s >> 6)*BC + b*CHK + (s & 63)) * ldc;
        } else {
            crow = (size_t)m * ldc;
        }
        size_t srow = (size_t)m * ldc;
        #pragma unroll
        for (int ni = 0; ni < NI; ++ni) {
            int n = n0 + wn + ni*8 + tg*2;
            #pragma unroll
            for (int cc = 0; cc < 2; ++cc) {
                float v = accm[mi][ni][rr*2 + cc] + accc[mi][ni][rr*2 + cc];
                size_t idx  = crow + n + cc;
                size_t sidx = srow + n + cc;
                if constexpr (EP == 0) C[idx] = v;
                else if constexpr (EP == 1) { C[idx] = v; store_hl(Ch, Cl, idx, siluf(v)); }
                else if constexpr (EP == 2) {
                    float vv = __bfloat162float(x0h[sidx]) + __bfloat162float(x0l[sidx]);
                    store_hl(Ch, Cl, idx, scale * clip1f(v - vv));
                }
                else if constexpr (EP == 3) store_hl(Ch, Cl, idx, v * siluderivf(f0[sidx]));
                else if constexpr (EP == 4) {
                    float gg = clip1f(v);
                    float mn = etg * f1[idx] - lrg * gg;
                    f1[idx] = mn;
                    float w = (1.0f - alg) * f0[idx] + mn;
                    C[idx] = w;
                    store_hl(Ch, Cl, idx, w);
                }
                else if constexpr (EP == 5) store_hl(Ch, Cl, idx, siluf(v));
                else if constexpr (EP == 6) store_hl(Ch, Cl, idx, v);
                else if constexpr (EP == 7) C[idx] = siluf(v);
                else if constexpr (EP == 8) store_hl(Ch, Cl, idx, siluf(v));
            }
        }
    }
}

template<int BM,int BN,bool AKM,bool BKM,int EP>
__global__ __launch_bounds__(128,2)
void mgemm_k(const bf* __restrict__ Ah, const bf* __restrict__ Al, int lda,
             const bf* __restrict__ Bh, const bf* __restrict__ Bl, int ldb,
             float* __restrict__ C, bf* __restrict__ Ch, bf* __restrict__ Cl, int ldc,
             int K,
             const float* __restrict__ f0,
             const bf* __restrict__ x0h, const bf* __restrict__ x0l,
             float* __restrict__ f1,
             const float* __restrict__ gates, float scale, int base)
{
    extern __shared__ __align__(16) char dsm[];
    mgemm_core<BM,BN,AKM,BKM,EP>(dsm, Ah,Al,lda, Bh,Bl,ldb, C,Ch,Cl,ldc, K,
                                 f0,x0h,x0l,f1, gates, scale, base,
                                 blockIdx.y*BM, blockIdx.x*BN);
}

// fused weight updates (w2 grad + w1 grad), both EP4, 64x64 tiles, K=BC
__global__ __launch_bounds__(128,2)
void wupd_k(const bf* __restrict__ d2h, const bf* __restrict__ d2l,
            const bf* __restrict__ a1h, const bf* __restrict__ a1l,
            float* __restrict__ w2n, bf* __restrict__ w2nh, bf* __restrict__ w2nl,
            const float* __restrict__ w2o, float* __restrict__ m2,
            const bf* __restrict__ d1h, const bf* __restrict__ d1l,
            const bf* __restrict__ kth, const bf* __restrict__ ktl,
            float* __restrict__ w1n, bf* __restrict__ w1nh, bf* __restrict__ w1nl,
            const float* __restrict__ w1o, float* __restrict__ m1,
            const float* __restrict__ gates)
{
    extern __shared__ __align__(16) char dsm[];
    int bx = blockIdx.x;
    constexpr int T2 = (HIDN/64)*(DIMN/64);
    if (bx < T2) {
        int nt = bx % (HIDN/64), mt = bx / (HIDN/64);
        mgemm_core<64,64,false,false,4>(dsm, d2h,d2l,DIMN, a1h,a1l,HIDN,
                                        w2n,w2nh,w2nl,HIDN, BC,
                                        w2o,nullptr,nullptr,m2, gates, 0.f, 0,
                                        mt*64, nt*64);
    } else {
        int i = bx - T2;
        int nt = i % (DIMN/64), mt = i / (DIMN/64);
        mgemm_core<64,64,false,false,4>(dsm, d1h,d1l,HIDN, kth,ktl,DIMN,
                                        w1n,w1nh,w1nl,DIMN, BC,
                                        w1o,nullptr,nullptr,m1, gates, 0.f, 0,
                                        mt*64, nt*64);
    }
}

// ---------------- fp32 -> bf16 hi/lo pre-split ----------------
__global__ void split_k(const float* __restrict__ s, bf* __restrict__ h, bf* __restrict__ l, int n)
{
    int i = (blockIdx.x*256 + threadIdx.x)*4;
    if (i >= n) return;
    float4 v = *(const float4*)(s + i);
    float f[4] = {v.x, v.y, v.z, v.w};
    bf hv[4], lv[4];
    #pragma unroll
    for (int j = 0; j < 4; ++j) {
        hv[j] = __float2bfloat16_rn(f[j]);
        lv[j] = __float2bfloat16_rn(f[j] - __bfloat162float(hv[j]));
    }
    *(uint2*)(h + i) = *(uint2*)hv;
    *(uint2*)(l + i) = *(uint2*)lv;
}

// ---------------- l2 normalize fp32 row -> hi/lo bf16 ----------------
__global__ void l2norm_k(const float* __restrict__ src, bf* __restrict__ h, bf* __restrict__ l)
{
    int row = blockIdx.x;
    const float* r = src + (size_t)row * DIMN;
    int t = threadIdx.x;
    float4 v = *(const float4*)(r + t*4);
    float ss = v.x*v.x + v.y*v.y + v.z*v.z + v.w*v.w;
    __shared__ float red[256];
    red[t] = ss; __syncthreads();
    for (int o = 128; o > 0; o >>= 1) { if (t < o) red[t] += red[t+o]; __syncthreads(); }
    float inv = rsqrtf(red[0] + EPSN);
    float f[4] = {v.x*inv, v.y*inv, v.z*inv, v.w*inv};
    bf hv[4], lv[4];
    #pragma unroll
    for (int j = 0; j < 4; ++j) {
        hv[j] = __float2bfloat16_rn(f[j]);
        lv[j] = __float2bfloat16_rn(f[j] - __bfloat162float(hv[j]));
    }
    size_t o4 = (size_t)row * DIMN + t*4;
    *(uint2*)(h + o4) = *(uint2*)hv;
    *(uint2*)(l + o4) = *(uint2*)lv;
}

// ---------------- per-token gate dots ----------------
__global__ void gate_tok_k(const float* __restrict__ x,
                           const float* __restrict__ wlr,  const float* __restrict__ blr,
                           const float* __restrict__ wdec, const float* __restrict__ bdec,
                           const float* __restrict__ wmom, const float* __restrict__ bmom)
{
    int tok = blockIdx.x;
    int t = threadIdx.x;
    const float* xr = x + (size_t)tok * DIMN;
    float s0 = 0.f, s1 = 0.f, s2 = 0.f;
    for (int i = t; i < DIMN; i += 256) {
        float xi = xr[i];
        s0 += xi * wlr[i]; s1 += xi * wdec[i]; s2 += xi * wmom[i];
    }
    __shared__ float r0[256], r1[256], r2[256];
    r0[t] = s0; r1[t] = s1; r2[t] = s2; __syncthreads();
    for (int o = 128; o > 0; o >>= 1) {
        if (t < o) { r0[t] += r0[t+o]; r1[t] += r1[t+o]; r2[t] += r2[t+o]; }
        __syncthreads();
    }
    if (t == 0) {
        g_gate_tok[tok*3+0] = sigf(r0[0] + blr[0]);
        g_gate_tok[tok*3+1] = sigf(r1[0] + bdec[0]);
        g_gate_tok[tok*3+2] = sigf(r2[0] + bmom[0]);
    }
}

// ---------------- per-chunk gate means ----------------
__global__ void gate_chunk_k()
{
    int ch = blockIdx.x;
    int t = threadIdx.x;
    int b = t >> 6, ci = t & 63;
    int tok = b*SS + ch*CHK + ci;
    __shared__ float r0[256], r1[256], r2[256];
    r0[t] = g_gate_tok[tok*3+0];
    r1[t] = g_gate_tok[tok*3+1];
    r2[t] = g_gate_tok[tok*3+2];
    __syncthreads();
    for (int o = 128; o > 0; o >>= 1) {
        if (t < o) { r0[t] += r0[t+o]; r1[t] += r1[t+o]; r2[t] += r2[t+o]; }
        __syncthreads();
    }
    if (t == 0) {
        g_gates[ch*3+0] = r0[0] * (1.0f/BC);
        g_gates[ch*3+1] = r1[0] * (1.0f/BC);
        g_gates[ch*3+2] = r2[0] * (1.0f/BC);
    }
}

// smem sizes per config
#define SM_A64 (4*(2*64+2*64)*40*2)   // 81920  (64x64 cp.async, 4 stages)
#define SM_A32 (4*(2*32+2*64)*40*2)   // 61440  (32x64 cp.async)
#define SM_R32 (2*(2*32+2*64)*40*2)   // 30720  (32x64 reg path)
#define SM_R64 (2*(2*64+2*64)*40*2)   // 40960  (64x64 reg path / wupd)

// ---------------- host orchestration ----------------
extern "C" void kernel_launch(void* const* d_in, const int* in_sizes, int n_in,
                              void* d_out, int out_size)
{
    const float* x    = (const float*)d_in[0];
    const float* Wk   = (const float*)d_in[1];
    const float* Wv   = (const float*)d_in[2];
    const float* Wq   = (const float*)d_in[3];
    const float* Wout = (const float*)d_in[4];
    const float* W1   = (const float*)d_in[5];
    const float* W2   = (const float*)d_in[6];
    const float* Wlr  = (const float*)d_in[7];
    const float* blr  = (const float*)d_in[8];
    const float* Wdec = (const float*)d_in[9];
    const float* bdec = (const float*)d_in[10];
    const float* Wmom = (const float*)d_in[11];
    const float* bmom = (const float*)d_in[12];
    float* out = (float*)d_out;

    // one-time: aux stream + events, large-smem opt-in
    static cudaStream_t s2 = nullptr;
    static cudaEvent_t evA = nullptr, evB0 = nullptr, evB1 = nullptr;
    if (!s2) {
        cudaStreamCreateWithFlags(&s2, cudaStreamNonBlocking);
        cudaEventCreateWithFlags(&evA,  cudaEventDisableTiming);
        cudaEventCreateWithFlags(&evB0, cudaEventDisableTiming);
        cudaEventCreateWithFlags(&evB1, cudaEventDisableTiming);
        cudaFuncSetAttribute(mgemm_k<64,64,true,true,7>, cudaFuncAttributeMaxDynamicSharedMemorySize, SM_A64);
        cudaFuncSetAttribute(mgemm_k<64,64,true,true,8>, cudaFuncAttributeMaxDynamicSharedMemorySize, SM_A64);
        cudaFuncSetAttribute(mgemm_k<64,64,true,true,0>, cudaFuncAttributeMaxDynamicSharedMemorySize, SM_A64);
        cudaFuncSetAttribute(mgemm_k<32,64,true,true,1>, cudaFuncAttributeMaxDynamicSharedMemorySize, SM_A32);
        cudaFuncSetAttribute(mgemm_k<32,64,true,true,2>, cudaFuncAttributeMaxDynamicSharedMemorySize, SM_A32);
        cudaFuncSetAttribute(mgemm_k<32,64,true,true,5>, cudaFuncAttributeMaxDynamicSharedMemorySize, SM_A32);
        cudaFuncSetAttribute(mgemm_k<32,64,true,true,6>, cudaFuncAttributeMaxDynamicSharedMemorySize, SM_A32);
    }

    // resolve device-global addresses
    bf *xh,*xl,*wkh,*wkl,*wvh,*wvl,*wqh,*wql,*woh,*wol;
    bf *kph,*kpl,*qph,*qpl,*vph,*vpl;
    bf *a1h,*a1l,*d2h,*d2l,*d1h,*d1l,*aqh,*aql,*yh,*yl;
    float *kp,*qp,*h1,*m1,*m2,*gch;
    float *w1f0,*w1f1,*w2f0,*w2f1;
    bf *w1h0,*w1h1,*w1l0,*w1l1,*w2h0,*w2h1,*w2l0,*w2l1;

    cudaGetSymbolAddress((void**)&xh, g_xh);   cudaGetSymbolAddress((void**)&xl, g_xl);
    cudaGetSymbolAddress((void**)&wkh,g_wkh);  cudaGetSymbolAddress((void**)&wkl,g_wkl);
    cudaGetSymbolAddress((void**)&wvh,g_wvh);  cudaGetSymbolAddress((void**)&wvl,g_wvl);
    cudaGetSymbolAddress((void**)&wqh,g_wqh);  cudaGetSymbolAddress((void**)&wql,g_wql);
    cudaGetSymbolAddress((void**)&woh,g_woh);  cudaGetSymbolAddress((void**)&wol,g_wol);
    cudaGetSymbolAddress((void**)&kp, g_kp);   cudaGetSymbolAddress((void**)&qp, g_qp);
    cudaGetSymbolAddress((void**)&kph,g_kph);  cudaGetSymbolAddress((void**)&kpl,g_kpl);
    cudaGetSymbolAddress((void**)&qph,g_qph);  cudaGetSymbolAddress((void**)&qpl,g_qpl);
    cudaGetSymbolAddress((void**)&vph,g_vph);  cudaGetSymbolAddress((void**)&vpl,g_vpl);
    cudaGetSymbolAddress((void**)&h1, g_h1);
    cudaGetSymbolAddress((void**)&a1h,g_a1h);  cudaGetSymbolAddress((void**)&a1l,g_a1l);
    cudaGetSymbolAddress((void**)&d2h,g_d2h);  cudaGetSymbolAddress((void**)&d2l,g_d2l);
    cudaGetSymbolAddress((void**)&d1h,g_d1h);  cudaGetSymbolAddress((void**)&d1l,g_d1l);
    cudaGetSymbolAddress((void**)&aqh,g_aqh);  cudaGetSymbolAddress((void**)&aql,g_aql);
    cudaGetSymbolAddress((void**)&yh, g_yh);   cudaGetSymbolAddress((void**)&yl, g_yl);
    cudaGetSymbolAddress((void**)&m1, g_m1);   cudaGetSymbolAddress((void**)&m2, g_m2);
    cudaGetSymbolAddress((void**)&gch,g_gates);
    { void* p;
      cudaGetSymbolAddress(&p, g_w1f); w1f0=(float*)p; w1f1=w1f0+HIDN*DIMN;
      cudaGetSymbolAddress(&p, g_w1h); w1h0=(bf*)p;    w1h1=w1h0+HIDN*DIMN;
      cudaGetSymbolAddress(&p, g_w1l); w1l0=(bf*)p;    w1l1=w1l0+HIDN*DIMN;
      cudaGetSymbolAddress(&p, g_w2f); w2f0=(float*)p; w2f1=w2f0+DIMN*HIDN;
      cudaGetSymbolAddress(&p, g_w2h); w2h0=(bf*)p;    w2h1=w2h0+DIMN*HIDN;
      cudaGetSymbolAddress(&p, g_w2l); w2l0=(bf*)p;    w2l1=w2l0+DIMN*HIDN;
    }

    cudaMemsetAsync(m1, 0, sizeof(float)*HIDN*DIMN);
    cudaMemsetAsync(m2, 0, sizeof(float)*DIMN*HIDN);

    // pre-split inputs
    split_k<<<(NTOK*DIMN)/1024, 256>>>(x,    xh,  xl,  NTOK*DIMN);
    split_k<<<(DIMN*DIMN)/1024, 256>>>(Wk,   wkh, wkl, DIMN*DIMN);
    split_k<<<(DIMN*DIMN)/1024, 256>>>(Wv,   wvh, wvl, DIMN*DIMN);
    split_k<<<(DIMN*DIMN)/1024, 256>>>(Wq,   wqh, wql, DIMN*DIMN);
    split_k<<<(DIMN*DIMN)/1024, 256>>>(Wout, woh, wol, DIMN*DIMN);
    split_k<<<(HIDN*DIMN)/1024, 256>>>(W1,   w1h1, w1l1, HIDN*DIMN);
    split_k<<<(DIMN*HIDN)/1024, 256>>>(W2,   w2h1, w2l1, DIMN*HIDN);

    gate_tok_k<<<NTOK, 256>>>(x, Wlr, blr, Wdec, bdec, Wmom, bmom);
    gate_chunk_k<<<NCH, 256>>>();

    // projections
    dim3 gproj(DIMN/64, NTOK/64);
    mgemm_k<64,64,true,true,7><<<gproj,128,SM_A64>>>(xh,xl,DIMN, wkh,wkl,DIMN, kp,nullptr,nullptr,DIMN, DIMN, nullptr,nullptr,nullptr,nullptr, nullptr,0.f,0);
    mgemm_k<64,64,true,true,7><<<gproj,128,SM_A64>>>(xh,xl,DIMN, wqh,wql,DIMN, qp,nullptr,nullptr,DIMN, DIMN, nullptr,nullptr,nullptr,nullptr, nullptr,0.f,0);
    mgemm_k<64,64,true,true,8><<<gproj,128,SM_A64>>>(xh,xl,DIMN, wvh,wvl,DIMN, nullptr,vph,vpl,DIMN, DIMN, nullptr,nullptr,nullptr,nullptr, nullptr,0.f,0);
    l2norm_k<<<NTOK,256>>>(kp, kph, kpl);
    l2norm_k<<<NTOK,256>>>(qp, qph, qpl);

    for (int ch = 0; ch < NCH; ++ch) {
        size_t co = (size_t)ch*BC*DIMN;
        const bf *kth = kph+co, *ktl = kpl+co;
        const bf *qth = qph+co, *qtl = qpl+co;
        const bf *vth = vph+co, *vtl = vpl+co;
        int wi = ch & 1;
        int ri = 1 - wi;
        const float* w1o = (ch == 0) ? W1 : (ri ? w1f1 : w1f0);
        const float* w2o = (ch == 0) ? W2 : (ri ? w2f1 : w2f0);
        const bf *w1rh = ri ? w1h1 : w1h0, *w1rl = ri ? w1l1 : w1l0;
        const bf *w2rh = ri ? w2h1 : w2h0, *w2rl = ri ? w2l1 : w2l0;
        float* w1n = wi ? w1f1 : w1f0;
        float* w2n = wi ? w2f1 : w2f0;
        bf *w1nh = wi ? w1h1 : w1h0, *w1nl = wi ? w1l1 : w1l0;
        bf *w2nh = wi ? w2h1 : w2h0, *w2nl = wi ? w2l1 : w2l0;
        const float* gp3 = gch + ch*3;

        // forward + grads on stream 0
        mgemm_k<32,64,true,true,1><<<dim3(HIDN/64, BC/32),128,SM_A32>>>(
            kth,ktl,DIMN, w1rh,w1rl,DIMN, h1,a1h,a1l,HIDN, DIMN,
            nullptr,nullptr,nullptr,nullptr, nullptr,0.f,0);
        mgemm_k<32,64,true,true,2><<<dim3(DIMN/64, BC/32),128,SM_A32>>>(
            a1h,a1l,HIDN, w2rh,w2rl,HIDN, nullptr,d2h,d2l,DIMN, HIDN,
            nullptr,vth,vtl,nullptr, nullptr,SCALE_CONST,0);
        mgemm_k<32,64,true,false,3><<<dim3(HIDN/64, BC/32),128,SM_R32>>>(
            d2h,d2l,DIMN, w2rh,w2rl,HIDN, nullptr,d1h,d1l,HIDN, DIMN,
            h1,nullptr,nullptr,nullptr, nullptr,0.f,0);
        // wupd(ch) rewrites weight slot (ch&1): wait until retrieval of ch-2 (same slot) finished
        if (ch >= 2) cudaStreamWaitEvent(0, (ch & 1) ? evB1 : evB0, 0);
        wupd_k<<<(HIDN/64)*(DIMN/64)*2,128,SM_R64>>>(
            d2h,d2l, a1h,a1l, w2n,w2nh,w2nl, w2o,m2,
            d1h,d1l, kth,ktl, w1n,w1nh,w1nl, w1o,m1, gp3);
        // retrieval on stream 2, overlapped with next chunk's forward
        cudaEventRecord(evA, 0);
        cudaStreamWaitEvent(s2, evA, 0);
        mgemm_k<32,64,true,true,5><<<dim3(HIDN/64, BC/32),128,SM_A32,s2>>>(
            qth,qtl,DIMN, w1nh,w1nl,DIMN, nullptr,aqh,aql,HIDN, DIMN,
            nullptr,nullptr,nullptr,nullptr, nullptr,0.f,0);
        mgemm_k<32,64,true,true,6><<<dim3(DIMN/64, BC/32),128,SM_A32,s2>>>(
            aqh,aql,HIDN, w2nh,w2nl,HIDN, nullptr,yh,yl,DIMN, HIDN,
            nullptr,nullptr,nullptr,nullptr, nullptr,0.f,ch*CHK);
        cudaEventRecord((ch & 1) ? evB1 : evB0, s2);
    }

    // join retrieval stream, then output projection
    cudaStreamWaitEvent(0, ((NCH-1) & 1) ? evB1 : evB0, 0);
    mgemm_k<64,64,true,true,0><<<dim3(DIMN/64, NTOK/64),128,SM_A64>>>(
        yh,yl,DIMN, woh,wol,DIMN, out,nullptr,nullptr,DIMN, DIMN,
        nullptr,nullptr,nullptr,nullptr, nullptr,0.f,0);
}